// round 9
// baseline (speedup 1.0000x reference)
#include <cuda_runtime.h>
#include <math.h>
#include <float.h>
#include <stdint.h>

#define HID 128
#define MAX_NODES 50000
#define MAX_EDGES 800000

// ------------------------- scratch (static, no allocs) -------------------------
__device__ float g_A[MAX_NODES * HID];     // z @ Wd
__device__ float g_B[MAX_NODES * HID];     // z @ Ws
__device__ int   g_deg[MAX_NODES];
__device__ int   g_off[MAX_NODES + 1];
__device__ int   g_cur[MAX_NODES];
__device__ int   g_csr[MAX_EDGES];

// ------------------------- tf32 helpers (sm_80+ baseline PTX only) -------------------------
__device__ __forceinline__ uint32_t f2tf(float f) {
    uint32_t u;
    asm("cvt.rna.tf32.f32 %0, %1;" : "=r"(u) : "f"(f));
    return u;
}

__device__ __forceinline__ void mma_tf32(float* c, const uint32_t* a, uint32_t b0, uint32_t b1) {
    asm volatile(
        "mma.sync.aligned.m16n8k8.row.col.f32.tf32.tf32.f32 "
        "{%0,%1,%2,%3}, {%4,%5,%6,%7}, {%8,%9}, {%0,%1,%2,%3};"
        : "+f"(c[0]), "+f"(c[1]), "+f"(c[2]), "+f"(c[3])
        : "r"(a[0]), "r"(a[1]), "r"(a[2]), "r"(a[3]), "r"(b0), "r"(b1));
}

// tiling: CTA = 256 thr = 8 warps (4M x 2N), tile 128(M) x 128(N)
#define PAF 132    // hid pitch (132 % 32 == 4 -> frag loads conflict-free)
#define PAC 68     // chunk-A pitch (68 % 32 == 4)
#define PB  136    // B pitch, k-major (136 % 32 == 8 -> frag loads conflict-free)

// ------------------------- compute core: 8 k8-steps over one 64-K chunk -------------------------
__device__ __forceinline__ void mma_chunk(
    float acc[2][8][4], const uint32_t* __restrict__ Asm, int apitch, int acolBase,
    const uint32_t* __restrict__ Bsm, int wm, int wn, int g, int tg)
{
#pragma unroll
    for (int kk = 0; kk < 64; kk += 8) {
        uint32_t a[2][4];
#pragma unroll
        for (int mt = 0; mt < 2; mt++) {
            const uint32_t* ap = Asm + (wm + mt * 16 + g) * apitch + acolBase + kk + tg;
            a[mt][0] = ap[0];
            a[mt][1] = ap[8 * apitch];
            a[mt][2] = ap[4];
            a[mt][3] = ap[8 * apitch + 4];
        }
#pragma unroll
        for (int nt = 0; nt < 8; nt++) {
            const uint32_t b0 = Bsm[(kk + tg) * PB + wn + nt * 8 + g];
            const uint32_t b1 = Bsm[(kk + tg + 4) * PB + wn + nt * 8 + g];
            mma_tf32(acc[0][nt], a[0], b0, b1);
            mma_tf32(acc[1][nt], a[1], b0, b1);
        }
    }
}

// ------------------------- gemm2: load z tile once, emit g_A = z@Wd, g_B = z@Ws -------------------------
#define GEMM2_SMEM ((128 * PAF + 64 * PB) * 4)   // 102400 B -> 2 CTA/SM

__global__ __launch_bounds__(256, 2) void gemm2_kernel(
    const float* __restrict__ z, const float* __restrict__ Wm, int M)
{
    extern __shared__ uint32_t sm[];
    uint32_t* As = sm;                  // [128][PAF] full K=128
    uint32_t* Bs = sm + 128 * PAF;      // [64][PB] one K-chunk

    const int tid  = threadIdx.x;
    const int wid  = tid >> 5;
    const int lane = tid & 31;
    const int g    = lane >> 2;
    const int tg   = lane & 3;
    const int wm   = (wid & 3) << 5;
    const int wn   = (wid >> 2) << 6;
    const int rowBase = blockIdx.x * 128;

    // load full A tile (128 x 128), cvt tf32
#pragma unroll
    for (int it = 0; it < 16; it++) {
        const int i = it * 256 + tid;
        const int row = i >> 5;
        const int c4  = (i & 31) << 2;
        const int gr = rowBase + row;
        float4 v = make_float4(0.f, 0.f, 0.f, 0.f);
        if (gr < M) v = *(const float4*)(z + (size_t)gr * HID + c4);
        uint32_t* p = As + row * PAF + c4;
        p[0] = f2tf(v.x); p[1] = f2tf(v.y); p[2] = f2tf(v.z); p[3] = f2tf(v.w);
    }

    for (int w = 0; w < 2; w++) {
        const float* W = Wm + (size_t)w * 128 * HID;
        float acc[2][8][4];
#pragma unroll
        for (int mt = 0; mt < 2; mt++)
#pragma unroll
            for (int nt = 0; nt < 8; nt++)
#pragma unroll
                for (int i = 0; i < 4; i++) acc[mt][nt][i] = 0.f;

        for (int chunk = 0; chunk < 2; chunk++) {
#pragma unroll
            for (int it = 0; it < 8; it++) {
                const int i = it * 256 + tid;
                const int k  = i >> 5;
                const int n4 = (i & 31) << 2;
                const float4 v = *(const float4*)(W + (size_t)(chunk * 64 + k) * HID + n4);
                uint32_t* p = Bs + k * PB + n4;
                p[0] = f2tf(v.x); p[1] = f2tf(v.y); p[2] = f2tf(v.z); p[3] = f2tf(v.w);
            }
            __syncthreads();
            mma_chunk(acc, As, PAF, chunk * 64, Bs, wm, wn, g, tg);
            __syncthreads();
        }

        float* C = w ? g_B : g_A;
#pragma unroll
        for (int mt = 0; mt < 2; mt++) {
            const int r0 = rowBase + wm + mt * 16 + g;
            const int r1 = r0 + 8;
#pragma unroll
            for (int nt = 0; nt < 8; nt++) {
                const int cb = wn + nt * 8 + tg * 2;
                if (r0 < M) *(float2*)(C + (size_t)r0 * HID + cb) =
                    make_float2(acc[mt][nt][0], acc[mt][nt][1]);
                if (r1 < M) *(float2*)(C + (size_t)r1 * HID + cb) =
                    make_float2(acc[mt][nt][2], acc[mt][nt][3]);
            }
        }
    }
}

// ------------------------- fused mega-kernel -------------------------
// per CTA (128 node-rows):
//   1) acc  = z@W1a                 (2 K-chunks via mma)
//   2) aggT = A + bm + max_e(B[src]+w*ww)  gathered in-kernel, stored tf32 to smem (As1|As2)
//   3) acc += aggT@W1b              (2 K-chunks via mma)
//   4) hid  = tf32(relu(acc + b1))  -> smem
//   5) out  = hid@W2 + b2
// smem words: As1[128][PAC] @0, As2[128][PAC] @8704, Bs[64][PB] @17408  (104448 B)
//             hid[128][PAF] @0 (clobbers As1+As2)
#define FUSED_SMEM (104448)

__global__ __launch_bounds__(256, 2) void fused_mega_kernel(
    const float* __restrict__ z,
    const int* __restrict__ src, const float* __restrict__ ew,
    const float* __restrict__ Wm, const float* __restrict__ bm,
    const float* __restrict__ W1, const float* __restrict__ b1,
    const float* __restrict__ W2, const float* __restrict__ b2,
    float* __restrict__ out, int M)
{
    extern __shared__ uint32_t sm[];
    uint32_t* As1 = sm;                 // [128][PAC]
    uint32_t* As2 = sm + 8704;          // [128][PAC]
    uint32_t* Bs  = sm + 17408;         // [64][PB]
    uint32_t* hid = sm;                 // [128][PAF] (clobbers As1/As2)

    const int tid  = threadIdx.x;
    const int wid  = tid >> 5;
    const int lane = tid & 31;
    const int g    = lane >> 2;
    const int tg   = lane & 3;
    const int wm   = (wid & 3) << 5;
    const int wn   = (wid >> 2) << 6;
    const int rowBase = blockIdx.x * 128;

    float acc[2][8][4];
#pragma unroll
    for (int mt = 0; mt < 2; mt++)
#pragma unroll
        for (int nt = 0; nt < 8; nt++)
#pragma unroll
            for (int i = 0; i < 4; i++) acc[mt][nt][i] = 0.f;

    // ---- phase 1: acc = z @ W1a (K chunks 0,1) ----
    for (int chunk = 0; chunk < 2; chunk++) {
        const int kloc = chunk * 64;
#pragma unroll
        for (int it = 0; it < 8; it++) {
            const int i = it * 256 + tid;
            const int row = i >> 4;
            const int c4  = (i & 15) << 2;
            const int gr = rowBase + row;
            float4 v = make_float4(0.f, 0.f, 0.f, 0.f);
            if (gr < M) v = *(const float4*)(z + (size_t)gr * HID + kloc + c4);
            uint32_t* p = As1 + row * PAC + c4;
            p[0] = f2tf(v.x); p[1] = f2tf(v.y); p[2] = f2tf(v.z); p[3] = f2tf(v.w);
        }
#pragma unroll
        for (int it = 0; it < 8; it++) {
            const int i = it * 256 + tid;
            const int k  = i >> 5;
            const int n4 = (i & 31) << 2;
            const float4 v = *(const float4*)(W1 + (size_t)(kloc + k) * HID + n4);
            uint32_t* p = Bs + k * PB + n4;
            p[0] = f2tf(v.x); p[1] = f2tf(v.y); p[2] = f2tf(v.z); p[3] = f2tf(v.w);
        }
        __syncthreads();
        mma_chunk(acc, As1, PAC, 0, Bs, wm, wn, g, tg);
        __syncthreads();
    }

    // ---- phase 2: in-kernel segment-max; result as tf32 into As1 (cols 0-63) / As2 (cols 64-127) ----
    {
        const float4 ww4 = *(const float4*)(Wm + 256 * HID + lane * 4);
        const float4 bm4 = *(const float4*)(bm + lane * 4);
        for (int rr = wid; rr < 128; rr += 8) {
            const int n = rowBase + rr;
            int s0 = 0, s1 = 0;
            if (n < M) { s0 = g_off[n]; s1 = g_off[n + 1]; }
            float4 m = make_float4(-FLT_MAX, -FLT_MAX, -FLT_MAX, -FLT_MAX);
            for (int base = s0; base < s1; base += 32) {
                const int idx = base + lane;
                int sv = 0; float wv = 0.f;
                if (idx < s1) {
                    const int e = g_csr[idx];
                    sv = src[e];
                    wv = ew[e];
                }
                const int cnt = min(32, s1 - base);
                int j = 0;
                for (; j + 1 < cnt; j += 2) {
                    const int   sj0 = __shfl_sync(0xffffffffu, sv, j);
                    const float wj0 = __shfl_sync(0xffffffffu, wv, j);
                    const int   sj1 = __shfl_sync(0xffffffffu, sv, j + 1);
                    const float wj1 = __shfl_sync(0xffffffffu, wv, j + 1);
                    const float4 b0 = *(const float4*)(g_B + (size_t)sj0 * HID + lane * 4);
                    const float4 b1v = *(const float4*)(g_B + (size_t)sj1 * HID + lane * 4);
                    m.x = fmaxf(m.x, fmaf(wj0, ww4.x, b0.x));
                    m.y = fmaxf(m.y, fmaf(wj0, ww4.y, b0.y));
                    m.z = fmaxf(m.z, fmaf(wj0, ww4.z, b0.z));
                    m.w = fmaxf(m.w, fmaf(wj0, ww4.w, b0.w));
                    m.x = fmaxf(m.x, fmaf(wj1, ww4.x, b1v.x));
                    m.y = fmaxf(m.y, fmaf(wj1, ww4.y, b1v.y));
                    m.z = fmaxf(m.z, fmaf(wj1, ww4.z, b1v.z));
                    m.w = fmaxf(m.w, fmaf(wj1, ww4.w, b1v.w));
                }
                if (j < cnt) {
                    const int   sj = __shfl_sync(0xffffffffu, sv, j);
                    const float wj = __shfl_sync(0xffffffffu, wv, j);
                    const float4 b4 = *(const float4*)(g_B + (size_t)sj * HID + lane * 4);
                    m.x = fmaxf(m.x, fmaf(wj, ww4.x, b4.x));
                    m.y = fmaxf(m.y, fmaf(wj, ww4.y, b4.y));
                    m.z = fmaxf(m.z, fmaf(wj, ww4.z, b4.z));
                    m.w = fmaxf(m.w, fmaf(wj, ww4.w, b4.w));
                }
            }
            uint4 t;
            if (s1 > s0) {
                const float4 a4 = *(const float4*)(g_A + (size_t)n * HID + lane * 4);
                t.x = f2tf(a4.x + bm4.x + m.x);
                t.y = f2tf(a4.y + bm4.y + m.y);
                t.z = f2tf(a4.z + bm4.z + m.z);
                t.w = f2tf(a4.w + bm4.w + m.w);
            } else {
                t.x = 0u; t.y = 0u; t.z = 0u; t.w = 0u;
            }
            if (lane < 16) *(uint4*)(As1 + rr * PAC + lane * 4) = t;
            else           *(uint4*)(As2 + rr * PAC + (lane - 16) * 4) = t;
        }
    }
    __syncthreads();

    // ---- phase 3: acc += aggT @ W1b (K chunks 2,3) ----
    const float* W1b = W1 + (size_t)128 * HID;
    for (int chunk = 0; chunk < 2; chunk++) {
#pragma unroll
        for (int it = 0; it < 8; it++) {
            const int i = it * 256 + tid;
            const int k  = i >> 5;
            const int n4 = (i & 31) << 2;
            const float4 v = *(const float4*)(W1b + (size_t)(chunk * 64 + k) * HID + n4);
            uint32_t* p = Bs + k * PB + n4;
            p[0] = f2tf(v.x); p[1] = f2tf(v.y); p[2] = f2tf(v.z); p[3] = f2tf(v.w);
        }
        __syncthreads();
        mma_chunk(acc, chunk ? As2 : As1, PAC, 0, Bs, wm, wn, g, tg);
        __syncthreads();
    }

    // ---- phase 4: hid = tf32(relu(acc + b1)) ----
#pragma unroll
    for (int mt = 0; mt < 2; mt++) {
        const int lr0 = wm + mt * 16 + g;
        const int lr1 = lr0 + 8;
#pragma unroll
        for (int nt = 0; nt < 8; nt++) {
            const int cb = wn + nt * 8 + tg * 2;
            const float bb0 = b1[cb], bb1 = b1[cb + 1];
            uint2 v0, v1;
            v0.x = f2tf(fmaxf(acc[mt][nt][0] + bb0, 0.f));
            v0.y = f2tf(fmaxf(acc[mt][nt][1] + bb1, 0.f));
            v1.x = f2tf(fmaxf(acc[mt][nt][2] + bb0, 0.f));
            v1.y = f2tf(fmaxf(acc[mt][nt][3] + bb1, 0.f));
            *(uint2*)(hid + lr0 * PAF + cb) = v0;
            *(uint2*)(hid + lr1 * PAF + cb) = v1;
        }
    }
    __syncthreads();

    // ---- phase 5: out = hid @ W2 + b2 ----
#pragma unroll
    for (int mt = 0; mt < 2; mt++)
#pragma unroll
        for (int nt = 0; nt < 8; nt++)
#pragma unroll
            for (int i = 0; i < 4; i++) acc[mt][nt][i] = 0.f;

    for (int chunk = 0; chunk < 2; chunk++) {
#pragma unroll
        for (int it = 0; it < 8; it++) {
            const int i = it * 256 + tid;
            const int k  = i >> 5;
            const int n4 = (i & 31) << 2;
            const float4 v = *(const float4*)(W2 + (size_t)(chunk * 64 + k) * HID + n4);
            uint32_t* p = Bs + k * PB + n4;
            p[0] = f2tf(v.x); p[1] = f2tf(v.y); p[2] = f2tf(v.z); p[3] = f2tf(v.w);
        }
        __syncthreads();
        mma_chunk(acc, hid, PAF, chunk * 64, Bs, wm, wn, g, tg);
        __syncthreads();
    }

#pragma unroll
    for (int mt = 0; mt < 2; mt++) {
        const int r0 = rowBase + wm + mt * 16 + g;
        const int r1 = r0 + 8;
#pragma unroll
        for (int nt = 0; nt < 8; nt++) {
            const int cb = wn + nt * 8 + tg * 2;
            const float bb0 = b2[cb], bb1 = b2[cb + 1];
            if (r0 < M) *(float2*)(out + (size_t)r0 * HID + cb) =
                make_float2(acc[mt][nt][0] + bb0, acc[mt][nt][1] + bb1);
            if (r1 < M) *(float2*)(out + (size_t)r1 * HID + cb) =
                make_float2(acc[mt][nt][2] + bb0, acc[mt][nt][3] + bb1);
        }
    }
}

// ------------------------- CSR build -------------------------
__global__ void zero_deg_kernel(int nNodes)
{
    int i = blockIdx.x * blockDim.x + threadIdx.x;
    if (i < nNodes) g_deg[i] = 0;
}

__global__ void deg_kernel(const int* __restrict__ dst, int nE)
{
    int e = blockIdx.x * blockDim.x + threadIdx.x;
    if (e < nE) atomicAdd(&g_deg[dst[e]], 1);
}

__global__ __launch_bounds__(1024) void scan_kernel(int nNodes)
{
    __shared__ int warpPre[32];
    __shared__ int s_carry;
    const int tid = threadIdx.x;
    const int lane = tid & 31;
    const int wid = tid >> 5;
    if (tid == 0) s_carry = 0;
    __syncthreads();
    const int nChunks = (nNodes + 1023) >> 10;
    for (int c = 0; c < nChunks; c++) {
        const int i = (c << 10) + tid;
        const int v = (i < nNodes) ? g_deg[i] : 0;
        int incl = v;
#pragma unroll
        for (int o = 1; o < 32; o <<= 1) {
            int t = __shfl_up_sync(0xffffffffu, incl, o);
            if (lane >= o) incl += t;
        }
        if (lane == 31) warpPre[wid] = incl;
        __syncthreads();
        if (wid == 0) {
            int ws = warpPre[lane];
            int wincl = ws;
#pragma unroll
            for (int o = 1; o < 32; o <<= 1) {
                int t = __shfl_up_sync(0xffffffffu, wincl, o);
                if (lane >= o) wincl += t;
            }
            warpPre[lane] = wincl - ws;
        }
        __syncthreads();
        const int excl = s_carry + warpPre[wid] + incl - v;
        if (i < nNodes) { g_off[i] = excl; g_cur[i] = excl; }
        __syncthreads();
        if (tid == 1023) s_carry = excl + v;
        __syncthreads();
    }
    if (tid == 0) g_off[nNodes] = s_carry;
}

__global__ void scatter_kernel(const int* __restrict__ dst, int nE)
{
    int e = blockIdx.x * blockDim.x + threadIdx.x;
    if (e < nE) {
        int p = atomicAdd(&g_cur[dst[e]], 1);
        g_csr[p] = e;
    }
}

// ------------------------- launch -------------------------
extern "C" void kernel_launch(void* const* d_in, const int* in_sizes, int n_in,
                              void* d_out, int out_size)
{
    const float* z   = (const float*)d_in[0];
    const float* ew  = (const float*)d_in[1];
    const int*   esrc= (const int*)d_in[2];
    const int*   edst= (const int*)d_in[3];
    const float* Wm  = (const float*)d_in[4];
    const float* bm  = (const float*)d_in[5];
    const float* W1  = (const float*)d_in[6];
    const float* b1  = (const float*)d_in[7];
    const float* W2  = (const float*)d_in[8];
    const float* b2  = (const float*)d_in[9];
    float* out = (float*)d_out;

    const int nNodes = in_sizes[0] / HID;
    const int nEdges = in_sizes[1];

    cudaFuncSetAttribute(gemm2_kernel, cudaFuncAttributeMaxDynamicSharedMemorySize, GEMM2_SMEM);
    cudaFuncSetAttribute(fused_mega_kernel, cudaFuncAttributeMaxDynamicSharedMemorySize, FUSED_SMEM);

    // lazily-created side stream + fork/join events (host-side objects, no device mem)
    static cudaStream_t s_side = nullptr;
    static cudaEvent_t  s_evFork = nullptr, s_evCsr = nullptr;
    if (!s_side) {
        cudaStreamCreateWithFlags(&s_side, cudaStreamNonBlocking);
        cudaEventCreateWithFlags(&s_evFork, cudaEventDisableTiming);
        cudaEventCreateWithFlags(&s_evCsr, cudaEventDisableTiming);
    }

    const int gemmGrid = (nNodes + 127) / 128;
    const int edgeGrid = (nEdges + 255) / 256;
    const int nodeGrid = (nNodes + 255) / 256;

    // fork: CSR build (edge-only inputs) runs concurrently with gemm2 (z-only inputs)
    cudaEventRecord(s_evFork, 0);
    cudaStreamWaitEvent(s_side, s_evFork, 0);

    // side stream: CSR build
    zero_deg_kernel<<<nodeGrid, 256, 0, s_side>>>(nNodes);
    deg_kernel<<<edgeGrid, 256, 0, s_side>>>(edst, nEdges);
    scan_kernel<<<1, 1024, 0, s_side>>>(nNodes);
    scatter_kernel<<<edgeGrid, 256, 0, s_side>>>(edst, nEdges);
    cudaEventRecord(s_evCsr, s_side);

    // main stream: shared-A dual projection g_A = z@Wd, g_B = z@Ws
    gemm2_kernel<<<gemmGrid, 256, GEMM2_SMEM>>>(z, Wm, nNodes);

    // join: fused mega-kernel needs CSR + g_A/g_B
    cudaStreamWaitEvent(0, s_evCsr, 0);

    // fused: agg (in-kernel gather-max) + hidden = relu([z|agg]@W1+b1) + out = hidden@W2+b2
    fused_mega_kernel<<<gemmGrid, 256, FUSED_SMEM>>>(
        z, esrc, ew, Wm, bm, W1, b1, W2, b2, out, nNodes);
}

// round 10
// speedup vs baseline: 1.2203x; 1.2203x over previous
#include <cuda_runtime.h>
#include <math.h>
#include <float.h>
#include <stdint.h>

#define HID 128
#define MAX_NODES 50000
#define MAX_EDGES 800000

// ------------------------- scratch (static, no allocs) -------------------------
__device__ float g_A[MAX_NODES * HID];     // z @ Wd
__device__ float g_B[MAX_NODES * HID];     // z @ Ws
__device__ float g_agg[MAX_NODES * HID];
__device__ int   g_deg[MAX_NODES];
__device__ int   g_off[MAX_NODES + 1];
__device__ int   g_cur[MAX_NODES];
__device__ int   g_csr[MAX_EDGES];

// ------------------------- tf32 helpers (sm_80+ baseline PTX only) -------------------------
__device__ __forceinline__ uint32_t f2tf(float f) {
    uint32_t u;
    asm("cvt.rna.tf32.f32 %0, %1;" : "=r"(u) : "f"(f));
    return u;
}

__device__ __forceinline__ void mma_tf32(float* c, const uint32_t* a, uint32_t b0, uint32_t b1) {
    asm volatile(
        "mma.sync.aligned.m16n8k8.row.col.f32.tf32.tf32.f32 "
        "{%0,%1,%2,%3}, {%4,%5,%6,%7}, {%8,%9}, {%0,%1,%2,%3};"
        : "+f"(c[0]), "+f"(c[1]), "+f"(c[2]), "+f"(c[3])
        : "r"(a[0]), "r"(a[1]), "r"(a[2]), "r"(a[3]), "r"(b0), "r"(b1));
}

// tiling: CTA = 256 thr = 8 warps (4M x 2N), tile 64(M) x 128(N)
// warp tile 16x64: acc[8 nt][4]
#define PAF 132    // full-A / hid pitch (132 % 32 == 4 -> frag loads conflict-free)
#define PAC 68     // chunk-A pitch (68 % 32 == 4)
#define PB  136    // B pitch, k-major (136 % 32 == 8 -> frag loads conflict-free)

// ------------------------- compute core: 8 k8-steps over one 64-K chunk (1 m16 tile/warp) -------------------------
__device__ __forceinline__ void mma_chunk64(
    float acc[8][4], const uint32_t* __restrict__ Asm, int apitch, int acolBase,
    const uint32_t* __restrict__ Bsm, int wm, int wn, int g, int tg)
{
#pragma unroll
    for (int kk = 0; kk < 64; kk += 8) {
        uint32_t a[4];
        const uint32_t* ap = Asm + (wm + g) * apitch + acolBase + kk + tg;
        a[0] = ap[0];
        a[1] = ap[8 * apitch];
        a[2] = ap[4];
        a[3] = ap[8 * apitch + 4];
#pragma unroll
        for (int nt = 0; nt < 8; nt++) {
            const uint32_t b0 = Bsm[(kk + tg) * PB + wn + nt * 8 + g];
            const uint32_t b1 = Bsm[(kk + tg + 4) * PB + wn + nt * 8 + g];
            mma_tf32(acc[nt], a, b0, b1);
        }
    }
}

// ------------------------- gemm2: load z tile once, emit g_A = z@Wd, g_B = z@Ws -------------------------
// smem: As [64][PAF] full K (8448 w) + Bs [64][PB] (8704 w) = 17152 words = 68608 B -> 3 CTA/SM
#define GEMM2_SMEM (68608)

__global__ __launch_bounds__(256, 3) void gemm2_kernel(
    const float* __restrict__ z, const float* __restrict__ Wm, int M)
{
    extern __shared__ uint32_t sm[];
    uint32_t* As = sm;                  // [64][PAF] full K=128
    uint32_t* Bs = sm + 64 * PAF;       // [64][PB] one K-chunk

    const int tid  = threadIdx.x;
    const int wid  = tid >> 5;
    const int lane = tid & 31;
    const int g    = lane >> 2;
    const int tg   = lane & 3;
    const int wm   = (wid & 3) << 4;   // warp M offset: 0,16,32,48
    const int wn   = (wid >> 2) << 6;  // warp N offset: 0,64
    const int rowBase = blockIdx.x * 64;

    // load full A tile (64 x 128), cvt tf32
#pragma unroll
    for (int it = 0; it < 8; it++) {
        const int i = it * 256 + tid;
        const int row = i >> 5;
        const int c4  = (i & 31) << 2;
        const int gr = rowBase + row;
        float4 v = make_float4(0.f, 0.f, 0.f, 0.f);
        if (gr < M) v = *(const float4*)(z + (size_t)gr * HID + c4);
        uint32_t* p = As + row * PAF + c4;
        p[0] = f2tf(v.x); p[1] = f2tf(v.y); p[2] = f2tf(v.z); p[3] = f2tf(v.w);
    }

    for (int w = 0; w < 2; w++) {
        const float* W = Wm + (size_t)w * 128 * HID;
        float acc[8][4];
#pragma unroll
        for (int nt = 0; nt < 8; nt++)
#pragma unroll
            for (int i = 0; i < 4; i++) acc[nt][i] = 0.f;

        for (int chunk = 0; chunk < 2; chunk++) {
#pragma unroll
            for (int it = 0; it < 8; it++) {
                const int i = it * 256 + tid;
                const int k  = i >> 5;
                const int n4 = (i & 31) << 2;
                const float4 v = *(const float4*)(W + (size_t)(chunk * 64 + k) * HID + n4);
                uint32_t* p = Bs + k * PB + n4;
                p[0] = f2tf(v.x); p[1] = f2tf(v.y); p[2] = f2tf(v.z); p[3] = f2tf(v.w);
            }
            __syncthreads();
            mma_chunk64(acc, As, PAF, chunk * 64, Bs, wm, wn, g, tg);
            __syncthreads();
        }

        float* C = w ? g_B : g_A;
        const int r0 = rowBase + wm + g;
        const int r1 = r0 + 8;
#pragma unroll
        for (int nt = 0; nt < 8; nt++) {
            const int cb = wn + nt * 8 + tg * 2;
            if (r0 < M) *(float2*)(C + (size_t)r0 * HID + cb) =
                make_float2(acc[nt][0], acc[nt][1]);
            if (r1 < M) *(float2*)(C + (size_t)r1 * HID + cb) =
                make_float2(acc[nt][2], acc[nt][3]);
        }
    }
}

// ------------------------- fused MLP: hidden = relu([z|agg]@W1 + b1); out = hidden@W2 + b2 -------------------------
// smem (words): stage1: As1 [64][PAC] @0 (4352) + Bs1 @4352 (8704)
//               stage2: hid [64][PAF] @0 (8448, clobbers As1+part of Bs1) + Bs2 @8448 (8704)
//               total 17152 words = 68608 B -> 3 CTA/SM
#define FUSED_SMEM (68608)

__global__ __launch_bounds__(256, 3) void fused_mlp_kernel(
    const float* __restrict__ z, const float* __restrict__ W1,
    const float* __restrict__ b1, const float* __restrict__ W2,
    const float* __restrict__ b2, float* __restrict__ out, int M)
{
    extern __shared__ uint32_t sm[];
    uint32_t* As1 = sm;                 // [64][PAC]
    uint32_t* Bs1 = sm + 4352;          // [64][PB]
    uint32_t* hid = sm;                 // [64][PAF] (clobbers As1/Bs1)
    uint32_t* Bs2 = sm + 8448;          // [64][PB]

    const int tid  = threadIdx.x;
    const int wid  = tid >> 5;
    const int lane = tid & 31;
    const int g    = lane >> 2;
    const int tg   = lane & 3;
    const int wm   = (wid & 3) << 4;
    const int wn   = (wid >> 2) << 6;
    const int rowBase = blockIdx.x * 64;

    float acc[8][4];
#pragma unroll
    for (int nt = 0; nt < 8; nt++)
#pragma unroll
        for (int i = 0; i < 4; i++) acc[nt][i] = 0.f;

    // ---- stage 1: K=256 over [z | agg] with W1[256][128] ----
    for (int chunk = 0; chunk < 4; chunk++) {
        const float* Asrc = (chunk < 2) ? z : g_agg;
        const int kloc = (chunk & 1) * 64;
#pragma unroll
        for (int it = 0; it < 4; it++) {
            const int i = it * 256 + tid;
            const int row = i >> 4;
            const int c4  = (i & 15) << 2;
            const int gr = rowBase + row;
            float4 v = make_float4(0.f, 0.f, 0.f, 0.f);
            if (gr < M) v = *(const float4*)(Asrc + (size_t)gr * HID + kloc + c4);
            uint32_t* p = As1 + row * PAC + c4;
            p[0] = f2tf(v.x); p[1] = f2tf(v.y); p[2] = f2tf(v.z); p[3] = f2tf(v.w);
        }
#pragma unroll
        for (int it = 0; it < 8; it++) {
            const int i = it * 256 + tid;
            const int k  = i >> 5;
            const int n4 = (i & 31) << 2;
            const float4 v = *(const float4*)(W1 + (size_t)(chunk * 64 + k) * HID + n4);
            uint32_t* p = Bs1 + k * PB + n4;
            p[0] = f2tf(v.x); p[1] = f2tf(v.y); p[2] = f2tf(v.z); p[3] = f2tf(v.w);
        }
        __syncthreads();
        mma_chunk64(acc, As1, PAC, 0, Bs1, wm, wn, g, tg);
        __syncthreads();
    }

    // ---- stage-1 epilogue: hid = tf32(relu(acc + b1)) ----
    {
        const int lr0 = wm + g;
        const int lr1 = lr0 + 8;
#pragma unroll
        for (int nt = 0; nt < 8; nt++) {
            const int cb = wn + nt * 8 + tg * 2;
            const float bb0 = b1[cb], bb1 = b1[cb + 1];
            uint2 v0, v1;
            v0.x = f2tf(fmaxf(acc[nt][0] + bb0, 0.f));
            v0.y = f2tf(fmaxf(acc[nt][1] + bb1, 0.f));
            v1.x = f2tf(fmaxf(acc[nt][2] + bb0, 0.f));
            v1.y = f2tf(fmaxf(acc[nt][3] + bb1, 0.f));
            *(uint2*)(hid + lr0 * PAF + cb) = v0;
            *(uint2*)(hid + lr1 * PAF + cb) = v1;
        }
    }
    __syncthreads();

    // ---- stage 2: out = hid @ W2 + b2 ----
#pragma unroll
    for (int nt = 0; nt < 8; nt++)
#pragma unroll
        for (int i = 0; i < 4; i++) acc[nt][i] = 0.f;

    for (int chunk = 0; chunk < 2; chunk++) {
#pragma unroll
        for (int it = 0; it < 8; it++) {
            const int i = it * 256 + tid;
            const int k  = i >> 5;
            const int n4 = (i & 31) << 2;
            const float4 v = *(const float4*)(W2 + (size_t)(chunk * 64 + k) * HID + n4);
            uint32_t* p = Bs2 + k * PB + n4;
            p[0] = f2tf(v.x); p[1] = f2tf(v.y); p[2] = f2tf(v.z); p[3] = f2tf(v.w);
        }
        __syncthreads();
        mma_chunk64(acc, hid, PAF, chunk * 64, Bs2, wm, wn, g, tg);
        __syncthreads();
    }

    {
        const int r0 = rowBase + wm + g;
        const int r1 = r0 + 8;
#pragma unroll
        for (int nt = 0; nt < 8; nt++) {
            const int cb = wn + nt * 8 + tg * 2;
            const float bb0 = b2[cb], bb1 = b2[cb + 1];
            if (r0 < M) *(float2*)(out + (size_t)r0 * HID + cb) =
                make_float2(acc[nt][0] + bb0, acc[nt][1] + bb1);
            if (r1 < M) *(float2*)(out + (size_t)r1 * HID + cb) =
                make_float2(acc[nt][2] + bb0, acc[nt][3] + bb1);
        }
    }
}

// ------------------------- CSR build -------------------------
__global__ void zero_deg_kernel(int nNodes)
{
    int i = blockIdx.x * blockDim.x + threadIdx.x;
    if (i < nNodes) g_deg[i] = 0;
}

__global__ void deg_kernel(const int* __restrict__ dst, int nE)
{
    int e = blockIdx.x * blockDim.x + threadIdx.x;
    if (e < nE) atomicAdd(&g_deg[dst[e]], 1);
}

__global__ __launch_bounds__(1024) void scan_kernel(int nNodes)
{
    __shared__ int warpPre[32];
    __shared__ int s_carry;
    const int tid = threadIdx.x;
    const int lane = tid & 31;
    const int wid = tid >> 5;
    if (tid == 0) s_carry = 0;
    __syncthreads();
    const int nChunks = (nNodes + 1023) >> 10;
    for (int c = 0; c < nChunks; c++) {
        const int i = (c << 10) + tid;
        const int v = (i < nNodes) ? g_deg[i] : 0;
        int incl = v;
#pragma unroll
        for (int o = 1; o < 32; o <<= 1) {
            int t = __shfl_up_sync(0xffffffffu, incl, o);
            if (lane >= o) incl += t;
        }
        if (lane == 31) warpPre[wid] = incl;
        __syncthreads();
        if (wid == 0) {
            int ws = warpPre[lane];
            int wincl = ws;
#pragma unroll
            for (int o = 1; o < 32; o <<= 1) {
                int t = __shfl_up_sync(0xffffffffu, wincl, o);
                if (lane >= o) wincl += t;
            }
            warpPre[lane] = wincl - ws;
        }
        __syncthreads();
        const int excl = s_carry + warpPre[wid] + incl - v;
        if (i < nNodes) { g_off[i] = excl; g_cur[i] = excl; }
        __syncthreads();
        if (tid == 1023) s_carry = excl + v;
        __syncthreads();
    }
    if (tid == 0) g_off[nNodes] = s_carry;
}

__global__ void scatter_kernel(const int* __restrict__ dst, int nE)
{
    int e = blockIdx.x * blockDim.x + threadIdx.x;
    if (e < nE) {
        int p = atomicAdd(&g_cur[dst[e]], 1);
        g_csr[p] = e;
    }
}

// ------------------------- per-node gather-max (edge loop unrolled 2x for MLP) -------------------------
__global__ __launch_bounds__(256) void agg_kernel(
    const int* __restrict__ src, const float* __restrict__ ew,
    const float* __restrict__ Wm, const float* __restrict__ bm,
    int nNodes)
{
    const int warpId = (blockIdx.x * blockDim.x + threadIdx.x) >> 5;
    const int lane = threadIdx.x & 31;
    if (warpId >= nNodes) return;
    const int n = warpId;
    const float4 ww4 = *(const float4*)(Wm + 256 * HID + lane * 4);
    const int s0 = g_off[n], s1 = g_off[n + 1];
    float4 m = make_float4(-FLT_MAX, -FLT_MAX, -FLT_MAX, -FLT_MAX);
    for (int base = s0; base < s1; base += 32) {
        const int idx = base + lane;
        int sv = 0; float wv = 0.f;
        if (idx < s1) {
            const int e = g_csr[idx];
            sv = src[e];
            wv = ew[e];
        }
        const int cnt = min(32, s1 - base);
        int j = 0;
        for (; j + 1 < cnt; j += 2) {
            const int   sj0 = __shfl_sync(0xffffffffu, sv, j);
            const float wj0 = __shfl_sync(0xffffffffu, wv, j);
            const int   sj1 = __shfl_sync(0xffffffffu, sv, j + 1);
            const float wj1 = __shfl_sync(0xffffffffu, wv, j + 1);
            const float4 b0 = *(const float4*)(g_B + (size_t)sj0 * HID + lane * 4);
            const float4 b1 = *(const float4*)(g_B + (size_t)sj1 * HID + lane * 4);
            m.x = fmaxf(m.x, fmaf(wj0, ww4.x, b0.x));
            m.y = fmaxf(m.y, fmaf(wj0, ww4.y, b0.y));
            m.z = fmaxf(m.z, fmaf(wj0, ww4.z, b0.z));
            m.w = fmaxf(m.w, fmaf(wj0, ww4.w, b0.w));
            m.x = fmaxf(m.x, fmaf(wj1, ww4.x, b1.x));
            m.y = fmaxf(m.y, fmaf(wj1, ww4.y, b1.y));
            m.z = fmaxf(m.z, fmaf(wj1, ww4.z, b1.z));
            m.w = fmaxf(m.w, fmaf(wj1, ww4.w, b1.w));
        }
        if (j < cnt) {
            const int   sj = __shfl_sync(0xffffffffu, sv, j);
            const float wj = __shfl_sync(0xffffffffu, wv, j);
            const float4 b4 = *(const float4*)(g_B + (size_t)sj * HID + lane * 4);
            m.x = fmaxf(m.x, fmaf(wj, ww4.x, b4.x));
            m.y = fmaxf(m.y, fmaf(wj, ww4.y, b4.y));
            m.z = fmaxf(m.z, fmaf(wj, ww4.z, b4.z));
            m.w = fmaxf(m.w, fmaf(wj, ww4.w, b4.w));
        }
    }
    float4 o;
    if (s1 > s0) {
        const float4 a4 = *(const float4*)(g_A + (size_t)n * HID + lane * 4);
        const float4 bm4 = *(const float4*)(bm + lane * 4);
        o = make_float4(a4.x + bm4.x + m.x, a4.y + bm4.y + m.y,
                        a4.z + bm4.z + m.z, a4.w + bm4.w + m.w);
    } else {
        o = make_float4(0.f, 0.f, 0.f, 0.f);
    }
    *(float4*)(g_agg + (size_t)n * HID + lane * 4) = o;
}

// ------------------------- launch -------------------------
extern "C" void kernel_launch(void* const* d_in, const int* in_sizes, int n_in,
                              void* d_out, int out_size)
{
    const float* z   = (const float*)d_in[0];
    const float* ew  = (const float*)d_in[1];
    const int*   esrc= (const int*)d_in[2];
    const int*   edst= (const int*)d_in[3];
    const float* Wm  = (const float*)d_in[4];
    const float* bm  = (const float*)d_in[5];
    const float* W1  = (const float*)d_in[6];
    const float* b1  = (const float*)d_in[7];
    const float* W2  = (const float*)d_in[8];
    const float* b2  = (const float*)d_in[9];
    float* out = (float*)d_out;

    const int nNodes = in_sizes[0] / HID;
    const int nEdges = in_sizes[1];

    cudaFuncSetAttribute(gemm2_kernel, cudaFuncAttributeMaxDynamicSharedMemorySize, GEMM2_SMEM);
    cudaFuncSetAttribute(fused_mlp_kernel, cudaFuncAttributeMaxDynamicSharedMemorySize, FUSED_SMEM);

    // lazily-created side stream + fork/join events (host-side objects, no device mem)
    static cudaStream_t s_side = nullptr;
    static cudaEvent_t  s_evFork = nullptr, s_evCsr = nullptr;
    if (!s_side) {
        cudaStreamCreateWithFlags(&s_side, cudaStreamNonBlocking);
        cudaEventCreateWithFlags(&s_evFork, cudaEventDisableTiming);
        cudaEventCreateWithFlags(&s_evCsr, cudaEventDisableTiming);
    }

    const int gemmGrid = (nNodes + 63) / 64;       // 64-row tiles -> 782 CTAs, 3 CTA/SM
    const int edgeGrid = (nEdges + 255) / 256;
    const int nodeGrid = (nNodes + 255) / 256;
    const int aggGrid  = (nNodes + 7) / 8;

    // fork: CSR build (edge-only inputs) runs concurrently with gemm2 (z-only inputs)
    cudaEventRecord(s_evFork, 0);
    cudaStreamWaitEvent(s_side, s_evFork, 0);

    // side stream: CSR build
    zero_deg_kernel<<<nodeGrid, 256, 0, s_side>>>(nNodes);
    deg_kernel<<<edgeGrid, 256, 0, s_side>>>(edst, nEdges);
    scan_kernel<<<1, 1024, 0, s_side>>>(nNodes);
    scatter_kernel<<<edgeGrid, 256, 0, s_side>>>(edst, nEdges);
    cudaEventRecord(s_evCsr, s_side);

    // main stream: shared-A dual projection g_A = z@Wd, g_B = z@Ws
    gemm2_kernel<<<gemmGrid, 256, GEMM2_SMEM>>>(z, Wm, nNodes);

    // join: agg needs both CSR and g_A/g_B
    cudaStreamWaitEvent(0, s_evCsr, 0);

    // segment max (gather form)
    agg_kernel<<<aggGrid, 256>>>(esrc, ew, Wm, bm, nNodes);

    // fused: hidden = relu([z|agg]@W1 + b1); out = hidden@W2 + b2
    fused_mlp_kernel<<<gemmGrid, 256, FUSED_SMEM>>>(z, W1, b1, W2, b2, out, nNodes);
}

// round 11
// speedup vs baseline: 1.3206x; 1.0822x over previous
#include <cuda_runtime.h>
#include <math.h>
#include <float.h>
#include <stdint.h>

#define HID 128
#define MAX_NODES 50000
#define MAX_EDGES 800000

// ------------------------- scratch (static, no allocs) -------------------------
__device__ float g_A[MAX_NODES * HID];     // z @ Wd
__device__ float g_B[MAX_NODES * HID];     // z @ Ws
__device__ float g_agg[MAX_NODES * HID];
__device__ int   g_deg[MAX_NODES];
__device__ int   g_off[MAX_NODES + 1];
__device__ int   g_cur[MAX_NODES];
__device__ int   g_csr[MAX_EDGES];

// ------------------------- tf32 helpers (sm_80+ baseline PTX only) -------------------------
__device__ __forceinline__ uint32_t f2tf(float f) {
    uint32_t u;
    asm("cvt.rna.tf32.f32 %0, %1;" : "=r"(u) : "f"(f));
    return u;
}

__device__ __forceinline__ void mma_tf32(float* c, const uint32_t* a, uint32_t b0, uint32_t b1) {
    asm volatile(
        "mma.sync.aligned.m16n8k8.row.col.f32.tf32.tf32.f32 "
        "{%0,%1,%2,%3}, {%4,%5,%6,%7}, {%8,%9}, {%0,%1,%2,%3};"
        : "+f"(c[0]), "+f"(c[1]), "+f"(c[2]), "+f"(c[3])
        : "r"(a[0]), "r"(a[1]), "r"(a[2]), "r"(a[3]), "r"(b0), "r"(b1));
}

// tiling: CTA = 256 thr = 8 warps (4M x 2N), tile 128(M) x 128(N)
#define PAF 132    // full-A / hid pitch (132 % 32 == 4 -> frag loads conflict-free)
#define PAC 68     // chunk-A pitch (68 % 32 == 4)
#define PB  136    // B pitch, k-major (136 % 32 == 8 -> frag loads conflict-free)

// ------------------------- compute core: 8 k8-steps over one 64-K chunk -------------------------
__device__ __forceinline__ void mma_chunk(
    float acc[2][8][4], const uint32_t* __restrict__ Asm, int apitch, int acolBase,
    const uint32_t* __restrict__ Bsm, int wm, int wn, int g, int tg)
{
#pragma unroll
    for (int kk = 0; kk < 64; kk += 8) {
        uint32_t a[2][4];
#pragma unroll
        for (int mt = 0; mt < 2; mt++) {
            const uint32_t* ap = Asm + (wm + mt * 16 + g) * apitch + acolBase + kk + tg;
            a[mt][0] = ap[0];
            a[mt][1] = ap[8 * apitch];
            a[mt][2] = ap[4];
            a[mt][3] = ap[8 * apitch + 4];
        }
#pragma unroll
        for (int nt = 0; nt < 8; nt++) {
            const uint32_t b0 = Bsm[(kk + tg) * PB + wn + nt * 8 + g];
            const uint32_t b1 = Bsm[(kk + tg + 4) * PB + wn + nt * 8 + g];
            mma_tf32(acc[0][nt], a[0], b0, b1);
            mma_tf32(acc[1][nt], a[1], b0, b1);
        }
    }
}

// ------------------------- gemm2: load z tile once, emit g_A = z@Wd, g_B = z@Ws -------------------------
#define GEMM2_SMEM ((128 * PAF + 64 * PB) * 4)   // 102400 B -> 2 CTA/SM

__global__ __launch_bounds__(256, 2) void gemm2_kernel(
    const float* __restrict__ z, const float* __restrict__ Wm, int M)
{
    extern __shared__ uint32_t sm[];
    uint32_t* As = sm;                  // [128][PAF] full K=128
    uint32_t* Bs = sm + 128 * PAF;      // [64][PB] one K-chunk

    const int tid  = threadIdx.x;
    const int wid  = tid >> 5;
    const int lane = tid & 31;
    const int g    = lane >> 2;
    const int tg   = lane & 3;
    const int wm   = (wid & 3) << 5;
    const int wn   = (wid >> 2) << 6;
    const int rowBase = blockIdx.x * 128;

    // load full A tile (128 x 128), cvt tf32
#pragma unroll
    for (int it = 0; it < 16; it++) {
        const int i = it * 256 + tid;
        const int row = i >> 5;
        const int c4  = (i & 31) << 2;
        const int gr = rowBase + row;
        float4 v = make_float4(0.f, 0.f, 0.f, 0.f);
        if (gr < M) v = *(const float4*)(z + (size_t)gr * HID + c4);
        uint32_t* p = As + row * PAF + c4;
        p[0] = f2tf(v.x); p[1] = f2tf(v.y); p[2] = f2tf(v.z); p[3] = f2tf(v.w);
    }

    for (int w = 0; w < 2; w++) {
        const float* W = Wm + (size_t)w * 128 * HID;
        float acc[2][8][4];
#pragma unroll
        for (int mt = 0; mt < 2; mt++)
#pragma unroll
            for (int nt = 0; nt < 8; nt++)
#pragma unroll
                for (int i = 0; i < 4; i++) acc[mt][nt][i] = 0.f;

        for (int chunk = 0; chunk < 2; chunk++) {
#pragma unroll
            for (int it = 0; it < 8; it++) {
                const int i = it * 256 + tid;
                const int k  = i >> 5;
                const int n4 = (i & 31) << 2;
                const float4 v = *(const float4*)(W + (size_t)(chunk * 64 + k) * HID + n4);
                uint32_t* p = Bs + k * PB + n4;
                p[0] = f2tf(v.x); p[1] = f2tf(v.y); p[2] = f2tf(v.z); p[3] = f2tf(v.w);
            }
            __syncthreads();
            mma_chunk(acc, As, PAF, chunk * 64, Bs, wm, wn, g, tg);
            __syncthreads();
        }

        float* C = w ? g_B : g_A;
#pragma unroll
        for (int mt = 0; mt < 2; mt++) {
            const int r0 = rowBase + wm + mt * 16 + g;
            const int r1 = r0 + 8;
#pragma unroll
            for (int nt = 0; nt < 8; nt++) {
                const int cb = wn + nt * 8 + tg * 2;
                if (r0 < M) *(float2*)(C + (size_t)r0 * HID + cb) =
                    make_float2(acc[mt][nt][0], acc[mt][nt][1]);
                if (r1 < M) *(float2*)(C + (size_t)r1 * HID + cb) =
                    make_float2(acc[mt][nt][2], acc[mt][nt][3]);
            }
        }
    }
}

// ------------------------- fused MLP: hidden = relu([z|agg]@W1 + b1); out = hidden@W2 + b2 -------------------------
#define FUSED_SMEM (104448)

__global__ __launch_bounds__(256, 2) void fused_mlp_kernel(
    const float* __restrict__ z, const float* __restrict__ W1,
    const float* __restrict__ b1, const float* __restrict__ W2,
    const float* __restrict__ b2, float* __restrict__ out,
    int rowStart, int M)
{
    extern __shared__ uint32_t sm[];
    uint32_t* As1 = sm;                 // [128][PAC]
    uint32_t* Bs1 = sm + 8704;          // [64][PB]
    uint32_t* hid = sm;                 // [128][PAF] (clobbers As1/Bs1)
    uint32_t* Bs2 = sm + 17408;         // [64][PB]

    const int tid  = threadIdx.x;
    const int wid  = tid >> 5;
    const int lane = tid & 31;
    const int g    = lane >> 2;
    const int tg   = lane & 3;
    const int wm   = (wid & 3) << 5;
    const int wn   = (wid >> 2) << 6;
    const int rowBase = rowStart + blockIdx.x * 128;

    float acc[2][8][4];
#pragma unroll
    for (int mt = 0; mt < 2; mt++)
#pragma unroll
        for (int nt = 0; nt < 8; nt++)
#pragma unroll
            for (int i = 0; i < 4; i++) acc[mt][nt][i] = 0.f;

    // ---- stage 1: K=256 over [z | agg] with W1[256][128] ----
    for (int chunk = 0; chunk < 4; chunk++) {
        const float* Asrc = (chunk < 2) ? z : g_agg;
        const int kloc = (chunk & 1) * 64;
#pragma unroll
        for (int it = 0; it < 8; it++) {
            const int i = it * 256 + tid;
            const int row = i >> 4;
            const int c4  = (i & 15) << 2;
            const int gr = rowBase + row;
            float4 v = make_float4(0.f, 0.f, 0.f, 0.f);
            if (gr < M) v = *(const float4*)(Asrc + (size_t)gr * HID + kloc + c4);
            uint32_t* p = As1 + row * PAC + c4;
            p[0] = f2tf(v.x); p[1] = f2tf(v.y); p[2] = f2tf(v.z); p[3] = f2tf(v.w);
        }
#pragma unroll
        for (int it = 0; it < 8; it++) {
            const int i = it * 256 + tid;
            const int k  = i >> 5;
            const int n4 = (i & 31) << 2;
            const float4 v = *(const float4*)(W1 + (size_t)(chunk * 64 + k) * HID + n4);
            uint32_t* p = Bs1 + k * PB + n4;
            p[0] = f2tf(v.x); p[1] = f2tf(v.y); p[2] = f2tf(v.z); p[3] = f2tf(v.w);
        }
        __syncthreads();
        mma_chunk(acc, As1, PAC, 0, Bs1, wm, wn, g, tg);
        __syncthreads();
    }

    // ---- stage-1 epilogue: hid = tf32(relu(acc + b1)) ----
#pragma unroll
    for (int mt = 0; mt < 2; mt++) {
        const int lr0 = wm + mt * 16 + g;
        const int lr1 = lr0 + 8;
#pragma unroll
        for (int nt = 0; nt < 8; nt++) {
            const int cb = wn + nt * 8 + tg * 2;
            const float bb0 = b1[cb], bb1 = b1[cb + 1];
            uint2 v0, v1;
            v0.x = f2tf(fmaxf(acc[mt][nt][0] + bb0, 0.f));
            v0.y = f2tf(fmaxf(acc[mt][nt][1] + bb1, 0.f));
            v1.x = f2tf(fmaxf(acc[mt][nt][2] + bb0, 0.f));
            v1.y = f2tf(fmaxf(acc[mt][nt][3] + bb1, 0.f));
            *(uint2*)(hid + lr0 * PAF + cb) = v0;
            *(uint2*)(hid + lr1 * PAF + cb) = v1;
        }
    }
    __syncthreads();

    // ---- stage 2: out = hid @ W2 + b2 ----
#pragma unroll
    for (int mt = 0; mt < 2; mt++)
#pragma unroll
        for (int nt = 0; nt < 8; nt++)
#pragma unroll
            for (int i = 0; i < 4; i++) acc[mt][nt][i] = 0.f;

    for (int chunk = 0; chunk < 2; chunk++) {
#pragma unroll
        for (int it = 0; it < 8; it++) {
            const int i = it * 256 + tid;
            const int k  = i >> 5;
            const int n4 = (i & 31) << 2;
            const float4 v = *(const float4*)(W2 + (size_t)(chunk * 64 + k) * HID + n4);
            uint32_t* p = Bs2 + k * PB + n4;
            p[0] = f2tf(v.x); p[1] = f2tf(v.y); p[2] = f2tf(v.z); p[3] = f2tf(v.w);
        }
        __syncthreads();
        mma_chunk(acc, hid, PAF, chunk * 64, Bs2, wm, wn, g, tg);
        __syncthreads();
    }

#pragma unroll
    for (int mt = 0; mt < 2; mt++) {
        const int r0 = rowBase + wm + mt * 16 + g;
        const int r1 = r0 + 8;
#pragma unroll
        for (int nt = 0; nt < 8; nt++) {
            const int cb = wn + nt * 8 + tg * 2;
            const float bb0 = b2[cb], bb1 = b2[cb + 1];
            if (r0 < M) *(float2*)(out + (size_t)r0 * HID + cb) =
                make_float2(acc[mt][nt][0] + bb0, acc[mt][nt][1] + bb1);
            if (r1 < M) *(float2*)(out + (size_t)r1 * HID + cb) =
                make_float2(acc[mt][nt][2] + bb0, acc[mt][nt][3] + bb1);
        }
    }
}

// ------------------------- CSR build (low-footprint grid-stride) -------------------------
__global__ void zero_deg_kernel(int nNodes)
{
    for (int i = blockIdx.x * blockDim.x + threadIdx.x; i < nNodes; i += gridDim.x * blockDim.x)
        g_deg[i] = 0;
}

__global__ void deg_kernel(const int* __restrict__ dst, int nE)
{
    for (int e = blockIdx.x * blockDim.x + threadIdx.x; e < nE; e += gridDim.x * blockDim.x)
        atomicAdd(&g_deg[dst[e]], 1);
}

__global__ __launch_bounds__(1024) void scan_kernel(int nNodes)
{
    __shared__ int warpPre[32];
    __shared__ int s_carry;
    const int tid = threadIdx.x;
    const int lane = tid & 31;
    const int wid = tid >> 5;
    if (tid == 0) s_carry = 0;
    __syncthreads();
    const int nChunks = (nNodes + 1023) >> 10;
    for (int c = 0; c < nChunks; c++) {
        const int i = (c << 10) + tid;
        const int v = (i < nNodes) ? g_deg[i] : 0;
        int incl = v;
#pragma unroll
        for (int o = 1; o < 32; o <<= 1) {
            int t = __shfl_up_sync(0xffffffffu, incl, o);
            if (lane >= o) incl += t;
        }
        if (lane == 31) warpPre[wid] = incl;
        __syncthreads();
        if (wid == 0) {
            int ws = warpPre[lane];
            int wincl = ws;
#pragma unroll
            for (int o = 1; o < 32; o <<= 1) {
                int t = __shfl_up_sync(0xffffffffu, wincl, o);
                if (lane >= o) wincl += t;
            }
            warpPre[lane] = wincl - ws;
        }
        __syncthreads();
        const int excl = s_carry + warpPre[wid] + incl - v;
        if (i < nNodes) { g_off[i] = excl; g_cur[i] = excl; }
        __syncthreads();
        if (tid == 1023) s_carry = excl + v;
        __syncthreads();
    }
    if (tid == 0) g_off[nNodes] = s_carry;
}

__global__ void scatter_kernel(const int* __restrict__ dst, int nE)
{
    for (int e = blockIdx.x * blockDim.x + threadIdx.x; e < nE; e += gridDim.x * blockDim.x) {
        int p = atomicAdd(&g_cur[dst[e]], 1);
        g_csr[p] = e;
    }
}

// ------------------------- per-node gather-max over node range [nStart, nEnd) -------------------------
__global__ __launch_bounds__(256) void agg_kernel(
    const int* __restrict__ src, const float* __restrict__ ew,
    const float* __restrict__ Wm, const float* __restrict__ bm,
    int nStart, int nEnd)
{
    const int warpId = (blockIdx.x * blockDim.x + threadIdx.x) >> 5;
    const int lane = threadIdx.x & 31;
    const int n = nStart + warpId;
    if (n >= nEnd) return;
    const float4 ww4 = *(const float4*)(Wm + 256 * HID + lane * 4);
    const int s0 = g_off[n], s1 = g_off[n + 1];
    float4 m = make_float4(-FLT_MAX, -FLT_MAX, -FLT_MAX, -FLT_MAX);
    for (int base = s0; base < s1; base += 32) {
        const int idx = base + lane;
        int sv = 0; float wv = 0.f;
        if (idx < s1) {
            const int e = g_csr[idx];
            sv = src[e];
            wv = ew[e];
        }
        const int cnt = min(32, s1 - base);
        int j = 0;
        for (; j + 1 < cnt; j += 2) {
            const int   sj0 = __shfl_sync(0xffffffffu, sv, j);
            const float wj0 = __shfl_sync(0xffffffffu, wv, j);
            const int   sj1 = __shfl_sync(0xffffffffu, sv, j + 1);
            const float wj1 = __shfl_sync(0xffffffffu, wv, j + 1);
            const float4 b0 = *(const float4*)(g_B + (size_t)sj0 * HID + lane * 4);
            const float4 b1 = *(const float4*)(g_B + (size_t)sj1 * HID + lane * 4);
            m.x = fmaxf(m.x, fmaf(wj0, ww4.x, b0.x));
            m.y = fmaxf(m.y, fmaf(wj0, ww4.y, b0.y));
            m.z = fmaxf(m.z, fmaf(wj0, ww4.z, b0.z));
            m.w = fmaxf(m.w, fmaf(wj0, ww4.w, b0.w));
            m.x = fmaxf(m.x, fmaf(wj1, ww4.x, b1.x));
            m.y = fmaxf(m.y, fmaf(wj1, ww4.y, b1.y));
            m.z = fmaxf(m.z, fmaf(wj1, ww4.z, b1.z));
            m.w = fmaxf(m.w, fmaf(wj1, ww4.w, b1.w));
        }
        if (j < cnt) {
            const int   sj = __shfl_sync(0xffffffffu, sv, j);
            const float wj = __shfl_sync(0xffffffffu, wv, j);
            const float4 b4 = *(const float4*)(g_B + (size_t)sj * HID + lane * 4);
            m.x = fmaxf(m.x, fmaf(wj, ww4.x, b4.x));
            m.y = fmaxf(m.y, fmaf(wj, ww4.y, b4.y));
            m.z = fmaxf(m.z, fmaf(wj, ww4.z, b4.z));
            m.w = fmaxf(m.w, fmaf(wj, ww4.w, b4.w));
        }
    }
    float4 o;
    if (s1 > s0) {
        const float4 a4 = *(const float4*)(g_A + (size_t)n * HID + lane * 4);
        const float4 bm4 = *(const float4*)(bm + lane * 4);
        o = make_float4(a4.x + bm4.x + m.x, a4.y + bm4.y + m.y,
                        a4.z + bm4.z + m.z, a4.w + bm4.w + m.w);
    } else {
        o = make_float4(0.f, 0.f, 0.f, 0.f);
    }
    *(float4*)(g_agg + (size_t)n * HID + lane * 4) = o;
}

// ------------------------- launch -------------------------
extern "C" void kernel_launch(void* const* d_in, const int* in_sizes, int n_in,
                              void* d_out, int out_size)
{
    const float* z   = (const float*)d_in[0];
    const float* ew  = (const float*)d_in[1];
    const int*   esrc= (const int*)d_in[2];
    const int*   edst= (const int*)d_in[3];
    const float* Wm  = (const float*)d_in[4];
    const float* bm  = (const float*)d_in[5];
    const float* W1  = (const float*)d_in[6];
    const float* b1  = (const float*)d_in[7];
    const float* W2  = (const float*)d_in[8];
    const float* b2  = (const float*)d_in[9];
    float* out = (float*)d_out;

    const int nNodes = in_sizes[0] / HID;
    const int nEdges = in_sizes[1];

    cudaFuncSetAttribute(gemm2_kernel, cudaFuncAttributeMaxDynamicSharedMemorySize, GEMM2_SMEM);
    cudaFuncSetAttribute(fused_mlp_kernel, cudaFuncAttributeMaxDynamicSharedMemorySize, FUSED_SMEM);

    // lazily-created side stream + events (host-side objects, no device mem)
    static cudaStream_t s_side = nullptr;
    static cudaEvent_t  s_evFork = nullptr, s_evCsr = nullptr, s_evG = nullptr,
                        s_evA0 = nullptr, s_evEnd = nullptr;
    if (!s_side) {
        cudaStreamCreateWithFlags(&s_side, cudaStreamNonBlocking);
        cudaEventCreateWithFlags(&s_evFork, cudaEventDisableTiming);
        cudaEventCreateWithFlags(&s_evCsr, cudaEventDisableTiming);
        cudaEventCreateWithFlags(&s_evG, cudaEventDisableTiming);
        cudaEventCreateWithFlags(&s_evA0, cudaEventDisableTiming);
        cudaEventCreateWithFlags(&s_evEnd, cudaEventDisableTiming);
    }

    // node split at a 128-row tile boundary
    const int tiles = (nNodes + 127) / 128;
    const int t0 = tiles / 2;
    const int t1 = tiles - t0;
    const int r0 = t0 * 128;           // half0 = nodes [0, r0), half1 = [r0, nNodes)

    const int csrGrid = 296;           // low-footprint grid-stride (2 CTAs/SM)
    const int agg0Grid = (r0 + 7) / 8;
    const int agg1Grid = (nNodes - r0 + 7) / 8;

    // fork: CSR build (edge-only inputs) runs concurrently with gemm2 (z-only inputs)
    cudaEventRecord(s_evFork, 0);
    cudaStreamWaitEvent(s_side, s_evFork, 0);

    // side stream: CSR build
    zero_deg_kernel<<<csrGrid, 256, 0, s_side>>>(nNodes);
    deg_kernel<<<csrGrid, 256, 0, s_side>>>(edst, nEdges);
    scan_kernel<<<1, 1024, 0, s_side>>>(nNodes);
    scatter_kernel<<<csrGrid, 256, 0, s_side>>>(edst, nEdges);
    cudaEventRecord(s_evCsr, s_side);

    // main stream: shared-A dual projection g_A = z@Wd, g_B = z@Ws
    gemm2_kernel<<<tiles, 256, GEMM2_SMEM>>>(z, Wm, nNodes);
    cudaEventRecord(s_evG, 0);

    // main: agg half0 (needs CSR + g_A/g_B), then fused half0
    cudaStreamWaitEvent(0, s_evCsr, 0);
    agg_kernel<<<agg0Grid, 256>>>(esrc, ew, Wm, bm, 0, r0);
    cudaEventRecord(s_evA0, 0);
    fused_mlp_kernel<<<t0, 256, FUSED_SMEM>>>(z, W1, b1, W2, b2, out, 0, nNodes);

    // side: agg half1 starts after agg half0 (so it overlaps fused half0), then fused half1
    cudaStreamWaitEvent(s_side, s_evG, 0);
    cudaStreamWaitEvent(s_side, s_evA0, 0);
    agg_kernel<<<agg1Grid, 256, 0, s_side>>>(esrc, ew, Wm, bm, r0, nNodes);
    fused_mlp_kernel<<<t1, 256, FUSED_SMEM, s_side>>>(z, W1, b1, W2, b2, out, r0, nNodes);
    cudaEventRecord(s_evEnd, s_side);

    // join everything back onto the capture stream
    cudaStreamWaitEvent(0, s_evEnd, 0);
}

// round 12
// speedup vs baseline: 1.4407x; 1.0909x over previous
#include <cuda_runtime.h>
#include <cuda_fp16.h>
#include <math.h>
#include <float.h>
#include <stdint.h>

#define HID 128
#define MAX_NODES 50000
#define MAX_EDGES 800000

// ------------------------- scratch (static, no allocs) -------------------------
__device__ float   g_A[MAX_NODES * HID];       // z @ Wd (fp32)
__device__ __half2 g_Bh[MAX_NODES * (HID/2)];  // z @ Ws (fp16 storage)
__device__ __half2 g_aggh[MAX_NODES * (HID/2)];// agg result (fp16 storage)
__device__ int     g_deg[MAX_NODES];
__device__ int     g_off[MAX_NODES + 1];
__device__ int     g_cur[MAX_NODES];
__device__ int     g_csr[MAX_EDGES];

// ------------------------- tf32 helpers (sm_80+ baseline PTX only) -------------------------
__device__ __forceinline__ uint32_t f2tf(float f) {
    uint32_t u;
    asm("cvt.rna.tf32.f32 %0, %1;" : "=r"(u) : "f"(f));
    return u;
}

__device__ __forceinline__ void mma_tf32(float* c, const uint32_t* a, uint32_t b0, uint32_t b1) {
    asm volatile(
        "mma.sync.aligned.m16n8k8.row.col.f32.tf32.tf32.f32 "
        "{%0,%1,%2,%3}, {%4,%5,%6,%7}, {%8,%9}, {%0,%1,%2,%3};"
        : "+f"(c[0]), "+f"(c[1]), "+f"(c[2]), "+f"(c[3])
        : "r"(a[0]), "r"(a[1]), "r"(a[2]), "r"(a[3]), "r"(b0), "r"(b1));
}

// tiling: CTA = 256 thr = 8 warps (4M x 2N), tile 128(M) x 128(N)
#define PAF 132    // full-A / hid pitch (132 % 32 == 4 -> frag loads conflict-free)
#define PAC 68     // chunk-A pitch (68 % 32 == 4)
#define PB  136    // B pitch, k-major (136 % 32 == 8 -> frag loads conflict-free)

// ------------------------- compute core: 8 k8-steps over one 64-K chunk -------------------------
__device__ __forceinline__ void mma_chunk(
    float acc[2][8][4], const uint32_t* __restrict__ Asm, int apitch, int acolBase,
    const uint32_t* __restrict__ Bsm, int wm, int wn, int g, int tg)
{
#pragma unroll
    for (int kk = 0; kk < 64; kk += 8) {
        uint32_t a[2][4];
#pragma unroll
        for (int mt = 0; mt < 2; mt++) {
            const uint32_t* ap = Asm + (wm + mt * 16 + g) * apitch + acolBase + kk + tg;
            a[mt][0] = ap[0];
            a[mt][1] = ap[8 * apitch];
            a[mt][2] = ap[4];
            a[mt][3] = ap[8 * apitch + 4];
        }
#pragma unroll
        for (int nt = 0; nt < 8; nt++) {
            const uint32_t b0 = Bsm[(kk + tg) * PB + wn + nt * 8 + g];
            const uint32_t b1 = Bsm[(kk + tg + 4) * PB + wn + nt * 8 + g];
            mma_tf32(acc[0][nt], a[0], b0, b1);
            mma_tf32(acc[1][nt], a[1], b0, b1);
        }
    }
}

// ------------------------- gemm2: load z tile once, emit g_A = z@Wd (fp32), g_Bh = z@Ws (fp16) -------------------------
#define GEMM2_SMEM ((128 * PAF + 64 * PB) * 4)   // 102400 B -> 2 CTA/SM

__global__ __launch_bounds__(256, 2) void gemm2_kernel(
    const float* __restrict__ z, const float* __restrict__ Wm, int M)
{
    extern __shared__ uint32_t sm[];
    uint32_t* As = sm;                  // [128][PAF] full K=128
    uint32_t* Bs = sm + 128 * PAF;      // [64][PB] one K-chunk

    const int tid  = threadIdx.x;
    const int wid  = tid >> 5;
    const int lane = tid & 31;
    const int g    = lane >> 2;
    const int tg   = lane & 3;
    const int wm   = (wid & 3) << 5;
    const int wn   = (wid >> 2) << 6;
    const int rowBase = blockIdx.x * 128;

    // load full A tile (128 x 128), cvt tf32
#pragma unroll
    for (int it = 0; it < 16; it++) {
        const int i = it * 256 + tid;
        const int row = i >> 5;
        const int c4  = (i & 31) << 2;
        const int gr = rowBase + row;
        float4 v = make_float4(0.f, 0.f, 0.f, 0.f);
        if (gr < M) v = *(const float4*)(z + (size_t)gr * HID + c4);
        uint32_t* p = As + row * PAF + c4;
        p[0] = f2tf(v.x); p[1] = f2tf(v.y); p[2] = f2tf(v.z); p[3] = f2tf(v.w);
    }

    for (int w = 0; w < 2; w++) {
        const float* W = Wm + (size_t)w * 128 * HID;
        float acc[2][8][4];
#pragma unroll
        for (int mt = 0; mt < 2; mt++)
#pragma unroll
            for (int nt = 0; nt < 8; nt++)
#pragma unroll
                for (int i = 0; i < 4; i++) acc[mt][nt][i] = 0.f;

        for (int chunk = 0; chunk < 2; chunk++) {
#pragma unroll
            for (int it = 0; it < 8; it++) {
                const int i = it * 256 + tid;
                const int k  = i >> 5;
                const int n4 = (i & 31) << 2;
                const float4 v = *(const float4*)(W + (size_t)(chunk * 64 + k) * HID + n4);
                uint32_t* p = Bs + k * PB + n4;
                p[0] = f2tf(v.x); p[1] = f2tf(v.y); p[2] = f2tf(v.z); p[3] = f2tf(v.w);
            }
            __syncthreads();
            mma_chunk(acc, As, PAF, chunk * 64, Bs, wm, wn, g, tg);
            __syncthreads();
        }

#pragma unroll
        for (int mt = 0; mt < 2; mt++) {
            const int r0 = rowBase + wm + mt * 16 + g;
            const int r1 = r0 + 8;
#pragma unroll
            for (int nt = 0; nt < 8; nt++) {
                const int cb = wn + nt * 8 + tg * 2;
                if (w == 0) {
                    if (r0 < M) *(float2*)(g_A + (size_t)r0 * HID + cb) =
                        make_float2(acc[mt][nt][0], acc[mt][nt][1]);
                    if (r1 < M) *(float2*)(g_A + (size_t)r1 * HID + cb) =
                        make_float2(acc[mt][nt][2], acc[mt][nt][3]);
                } else {
                    if (r0 < M) g_Bh[(size_t)r0 * (HID/2) + (cb >> 1)] =
                        __floats2half2_rn(acc[mt][nt][0], acc[mt][nt][1]);
                    if (r1 < M) g_Bh[(size_t)r1 * (HID/2) + (cb >> 1)] =
                        __floats2half2_rn(acc[mt][nt][2], acc[mt][nt][3]);
                }
            }
        }
    }
}

// ------------------------- fused MLP: hidden = relu([z|agg]@W1 + b1); out = hidden@W2 + b2 -------------------------
#define FUSED_SMEM (104448)

__global__ __launch_bounds__(256, 2) void fused_mlp_kernel(
    const float* __restrict__ z, const float* __restrict__ W1,
    const float* __restrict__ b1, const float* __restrict__ W2,
    const float* __restrict__ b2, float* __restrict__ out, int M)
{
    extern __shared__ uint32_t sm[];
    uint32_t* As1 = sm;                 // [128][PAC]
    uint32_t* Bs1 = sm + 8704;          // [64][PB]
    uint32_t* hid = sm;                 // [128][PAF] (clobbers As1/Bs1)
    uint32_t* Bs2 = sm + 17408;         // [64][PB]

    const int tid  = threadIdx.x;
    const int wid  = tid >> 5;
    const int lane = tid & 31;
    const int g    = lane >> 2;
    const int tg   = lane & 3;
    const int wm   = (wid & 3) << 5;
    const int wn   = (wid >> 2) << 6;
    const int rowBase = blockIdx.x * 128;

    float acc[2][8][4];
#pragma unroll
    for (int mt = 0; mt < 2; mt++)
#pragma unroll
        for (int nt = 0; nt < 8; nt++)
#pragma unroll
            for (int i = 0; i < 4; i++) acc[mt][nt][i] = 0.f;

    // ---- stage 1: K=256 over [z | agg] with W1[256][128] ----
    for (int chunk = 0; chunk < 4; chunk++) {
        const int kloc = (chunk & 1) * 64;
#pragma unroll
        for (int it = 0; it < 8; it++) {
            const int i = it * 256 + tid;
            const int row = i >> 4;
            const int c4  = (i & 15) << 2;
            const int gr = rowBase + row;
            uint32_t* p = As1 + row * PAC + c4;
            if (chunk < 2) {
                float4 v = make_float4(0.f, 0.f, 0.f, 0.f);
                if (gr < M) v = *(const float4*)(z + (size_t)gr * HID + kloc + c4);
                p[0] = f2tf(v.x); p[1] = f2tf(v.y); p[2] = f2tf(v.z); p[3] = f2tf(v.w);
            } else {
                // agg stored fp16; fp16 -> fp32 -> tf32 is exact (fp16 subset of tf32)
                float2 f01 = make_float2(0.f, 0.f), f23 = make_float2(0.f, 0.f);
                if (gr < M) {
                    const uint2 hv = *(const uint2*)(g_aggh + (size_t)gr * (HID/2) + ((kloc + c4) >> 1));
                    f01 = __half22float2(*(const __half2*)&hv.x);
                    f23 = __half22float2(*(const __half2*)&hv.y);
                }
                p[0] = f2tf(f01.x); p[1] = f2tf(f01.y); p[2] = f2tf(f23.x); p[3] = f2tf(f23.y);
            }
        }
#pragma unroll
        for (int it = 0; it < 8; it++) {
            const int i = it * 256 + tid;
            const int k  = i >> 5;
            const int n4 = (i & 31) << 2;
            const float4 v = *(const float4*)(W1 + (size_t)(chunk * 64 + k) * HID + n4);
            uint32_t* p = Bs1 + k * PB + n4;
            p[0] = f2tf(v.x); p[1] = f2tf(v.y); p[2] = f2tf(v.z); p[3] = f2tf(v.w);
        }
        __syncthreads();
        mma_chunk(acc, As1, PAC, 0, Bs1, wm, wn, g, tg);
        __syncthreads();
    }

    // ---- stage-1 epilogue: hid = tf32(relu(acc + b1)) ----
#pragma unroll
    for (int mt = 0; mt < 2; mt++) {
        const int lr0 = wm + mt * 16 + g;
        const int lr1 = lr0 + 8;
#pragma unroll
        for (int nt = 0; nt < 8; nt++) {
            const int cb = wn + nt * 8 + tg * 2;
            const float bb0 = b1[cb], bb1 = b1[cb + 1];
            uint2 v0, v1;
            v0.x = f2tf(fmaxf(acc[mt][nt][0] + bb0, 0.f));
            v0.y = f2tf(fmaxf(acc[mt][nt][1] + bb1, 0.f));
            v1.x = f2tf(fmaxf(acc[mt][nt][2] + bb0, 0.f));
            v1.y = f2tf(fmaxf(acc[mt][nt][3] + bb1, 0.f));
            *(uint2*)(hid + lr0 * PAF + cb) = v0;
            *(uint2*)(hid + lr1 * PAF + cb) = v1;
        }
    }
    __syncthreads();

    // ---- stage 2: out = hid @ W2 + b2 ----
#pragma unroll
    for (int mt = 0; mt < 2; mt++)
#pragma unroll
        for (int nt = 0; nt < 8; nt++)
#pragma unroll
            for (int i = 0; i < 4; i++) acc[mt][nt][i] = 0.f;

    for (int chunk = 0; chunk < 2; chunk++) {
#pragma unroll
        for (int it = 0; it < 8; it++) {
            const int i = it * 256 + tid;
            const int k  = i >> 5;
            const int n4 = (i & 31) << 2;
            const float4 v = *(const float4*)(W2 + (size_t)(chunk * 64 + k) * HID + n4);
            uint32_t* p = Bs2 + k * PB + n4;
            p[0] = f2tf(v.x); p[1] = f2tf(v.y); p[2] = f2tf(v.z); p[3] = f2tf(v.w);
        }
        __syncthreads();
        mma_chunk(acc, hid, PAF, chunk * 64, Bs2, wm, wn, g, tg);
        __syncthreads();
    }

#pragma unroll
    for (int mt = 0; mt < 2; mt++) {
        const int r0 = rowBase + wm + mt * 16 + g;
        const int r1 = r0 + 8;
#pragma unroll
        for (int nt = 0; nt < 8; nt++) {
            const int cb = wn + nt * 8 + tg * 2;
            const float bb0 = b2[cb], bb1 = b2[cb + 1];
            if (r0 < M) *(float2*)(out + (size_t)r0 * HID + cb) =
                make_float2(acc[mt][nt][0] + bb0, acc[mt][nt][1] + bb1);
            if (r1 < M) *(float2*)(out + (size_t)r1 * HID + cb) =
                make_float2(acc[mt][nt][2] + bb0, acc[mt][nt][3] + bb1);
        }
    }
}

// ------------------------- CSR build -------------------------
__global__ void zero_deg_kernel(int nNodes)
{
    int i = blockIdx.x * blockDim.x + threadIdx.x;
    if (i < nNodes) g_deg[i] = 0;
}

__global__ void deg_kernel(const int* __restrict__ dst, int nE)
{
    int e = blockIdx.x * blockDim.x + threadIdx.x;
    if (e < nE) atomicAdd(&g_deg[dst[e]], 1);
}

__global__ __launch_bounds__(1024) void scan_kernel(int nNodes)
{
    __shared__ int warpPre[32];
    __shared__ int s_carry;
    const int tid = threadIdx.x;
    const int lane = tid & 31;
    const int wid = tid >> 5;
    if (tid == 0) s_carry = 0;
    __syncthreads();
    const int nChunks = (nNodes + 1023) >> 10;
    for (int c = 0; c < nChunks; c++) {
        const int i = (c << 10) + tid;
        const int v = (i < nNodes) ? g_deg[i] : 0;
        int incl = v;
#pragma unroll
        for (int o = 1; o < 32; o <<= 1) {
            int t = __shfl_up_sync(0xffffffffu, incl, o);
            if (lane >= o) incl += t;
        }
        if (lane == 31) warpPre[wid] = incl;
        __syncthreads();
        if (wid == 0) {
            int ws = warpPre[lane];
            int wincl = ws;
#pragma unroll
            for (int o = 1; o < 32; o <<= 1) {
                int t = __shfl_up_sync(0xffffffffu, wincl, o);
                if (lane >= o) wincl += t;
            }
            warpPre[lane] = wincl - ws;
        }
        __syncthreads();
        const int excl = s_carry + warpPre[wid] + incl - v;
        if (i < nNodes) { g_off[i] = excl; g_cur[i] = excl; }
        __syncthreads();
        if (tid == 1023) s_carry = excl + v;
        __syncthreads();
    }
    if (tid == 0) g_off[nNodes] = s_carry;
}

__global__ void scatter_kernel(const int* __restrict__ dst, int nE)
{
    int e = blockIdx.x * blockDim.x + threadIdx.x;
    if (e < nE) {
        int p = atomicAdd(&g_cur[dst[e]], 1);
        g_csr[p] = e;
    }
}

// ------------------------- per-node gather-max (fp16 g_B rows, edge loop unrolled 2x) -------------------------
__global__ __launch_bounds__(256) void agg_kernel(
    const int* __restrict__ src, const float* __restrict__ ew,
    const float* __restrict__ Wm, const float* __restrict__ bm,
    int nNodes)
{
    const int warpId = (blockIdx.x * blockDim.x + threadIdx.x) >> 5;
    const int lane = threadIdx.x & 31;
    if (warpId >= nNodes) return;
    const int n = warpId;
    const float4 ww4 = *(const float4*)(Wm + 256 * HID + lane * 4);
    const int s0 = g_off[n], s1 = g_off[n + 1];
    float4 m = make_float4(-FLT_MAX, -FLT_MAX, -FLT_MAX, -FLT_MAX);
    for (int base = s0; base < s1; base += 32) {
        const int idx = base + lane;
        int sv = 0; float wv = 0.f;
        if (idx < s1) {
            const int e = g_csr[idx];
            sv = src[e];
            wv = ew[e];
        }
        const int cnt = min(32, s1 - base);
        int j = 0;
        for (; j + 1 < cnt; j += 2) {
            const int   sj0 = __shfl_sync(0xffffffffu, sv, j);
            const float wj0 = __shfl_sync(0xffffffffu, wv, j);
            const int   sj1 = __shfl_sync(0xffffffffu, sv, j + 1);
            const float wj1 = __shfl_sync(0xffffffffu, wv, j + 1);
            const uint2 h0 = *(const uint2*)(g_Bh + (size_t)sj0 * (HID/2) + lane * 2);
            const uint2 h1 = *(const uint2*)(g_Bh + (size_t)sj1 * (HID/2) + lane * 2);
            const float2 b0a = __half22float2(*(const __half2*)&h0.x);
            const float2 b0b = __half22float2(*(const __half2*)&h0.y);
            const float2 b1a = __half22float2(*(const __half2*)&h1.x);
            const float2 b1b = __half22float2(*(const __half2*)&h1.y);
            m.x = fmaxf(m.x, fmaf(wj0, ww4.x, b0a.x));
            m.y = fmaxf(m.y, fmaf(wj0, ww4.y, b0a.y));
            m.z = fmaxf(m.z, fmaf(wj0, ww4.z, b0b.x));
            m.w = fmaxf(m.w, fmaf(wj0, ww4.w, b0b.y));
            m.x = fmaxf(m.x, fmaf(wj1, ww4.x, b1a.x));
            m.y = fmaxf(m.y, fmaf(wj1, ww4.y, b1a.y));
            m.z = fmaxf(m.z, fmaf(wj1, ww4.z, b1b.x));
            m.w = fmaxf(m.w, fmaf(wj1, ww4.w, b1b.y));
        }
        if (j < cnt) {
            const int   sj = __shfl_sync(0xffffffffu, sv, j);
            const float wj = __shfl_sync(0xffffffffu, wv, j);
            const uint2 h0 = *(const uint2*)(g_Bh + (size_t)sj * (HID/2) + lane * 2);
            const float2 b0a = __half22float2(*(const __half2*)&h0.x);
            const float2 b0b = __half22float2(*(const __half2*)&h0.y);
            m.x = fmaxf(m.x, fmaf(wj, ww4.x, b0a.x));
            m.y = fmaxf(m.y, fmaf(wj, ww4.y, b0a.y));
            m.z = fmaxf(m.z, fmaf(wj, ww4.z, b0b.x));
            m.w = fmaxf(m.w, fmaf(wj, ww4.w, b0b.y));
        }
    }
    uint2 o;
    if (s1 > s0) {
        const float4 a4 = *(const float4*)(g_A + (size_t)n * HID + lane * 4);
        const float4 bm4 = *(const float4*)(bm + lane * 4);
        const __half2 o01 = __floats2half2_rn(a4.x + bm4.x + m.x, a4.y + bm4.y + m.y);
        const __half2 o23 = __floats2half2_rn(a4.z + bm4.z + m.z, a4.w + bm4.w + m.w);
        o.x = *(const uint32_t*)&o01;
        o.y = *(const uint32_t*)&o23;
    } else {
        o.x = 0u; o.y = 0u;
    }
    *(uint2*)(g_aggh + (size_t)n * (HID/2) + lane * 2) = o;
}

// ------------------------- launch -------------------------
extern "C" void kernel_launch(void* const* d_in, const int* in_sizes, int n_in,
                              void* d_out, int out_size)
{
    const float* z   = (const float*)d_in[0];
    const float* ew  = (const float*)d_in[1];
    const int*   esrc= (const int*)d_in[2];
    const int*   edst= (const int*)d_in[3];
    const float* Wm  = (const float*)d_in[4];
    const float* bm  = (const float*)d_in[5];
    const float* W1  = (const float*)d_in[6];
    const float* b1  = (const float*)d_in[7];
    const float* W2  = (const float*)d_in[8];
    const float* b2  = (const float*)d_in[9];
    float* out = (float*)d_out;

    const int nNodes = in_sizes[0] / HID;
    const int nEdges = in_sizes[1];

    cudaFuncSetAttribute(gemm2_kernel, cudaFuncAttributeMaxDynamicSharedMemorySize, GEMM2_SMEM);
    cudaFuncSetAttribute(fused_mlp_kernel, cudaFuncAttributeMaxDynamicSharedMemorySize, FUSED_SMEM);

    // lazily-created side stream + fork/join events (host-side objects, no device mem)
    static cudaStream_t s_side = nullptr;
    static cudaEvent_t  s_evFork = nullptr, s_evCsr = nullptr;
    if (!s_side) {
        cudaStreamCreateWithFlags(&s_side, cudaStreamNonBlocking);
        cudaEventCreateWithFlags(&s_evFork, cudaEventDisableTiming);
        cudaEventCreateWithFlags(&s_evCsr, cudaEventDisableTiming);
    }

    const int gemmGrid = (nNodes + 127) / 128;
    const int edgeGrid = (nEdges + 255) / 256;
    const int nodeGrid = (nNodes + 255) / 256;
    const int aggGrid  = (nNodes + 7) / 8;

    // fork: CSR build (edge-only inputs) runs concurrently with gemm2 (z-only inputs)
    cudaEventRecord(s_evFork, 0);
    cudaStreamWaitEvent(s_side, s_evFork, 0);

    // side stream: CSR build
    zero_deg_kernel<<<nodeGrid, 256, 0, s_side>>>(nNodes);
    deg_kernel<<<edgeGrid, 256, 0, s_side>>>(edst, nEdges);
    scan_kernel<<<1, 1024, 0, s_side>>>(nNodes);
    scatter_kernel<<<edgeGrid, 256, 0, s_side>>>(edst, nEdges);
    cudaEventRecord(s_evCsr, s_side);

    // main stream: shared-A dual projection g_A = z@Wd (fp32), g_Bh = z@Ws (fp16)
    gemm2_kernel<<<gemmGrid, 256, GEMM2_SMEM>>>(z, Wm, nNodes);

    // join: agg needs both CSR and g_A/g_Bh
    cudaStreamWaitEvent(0, s_evCsr, 0);

    // segment max (gather form, fp16 rows)
    agg_kernel<<<aggGrid, 256>>>(esrc, ew, Wm, bm, nNodes);

    // fused: hidden = relu([z|agg]@W1 + b1); out = hidden@W2 + b2
    fused_mlp_kernel<<<gemmGrid, 256, FUSED_SMEM>>>(z, W1, b1, W2, b2, out, nNodes);
}

// round 13
// speedup vs baseline: 1.5441x; 1.0718x over previous
#include <cuda_runtime.h>
#include <cuda_fp16.h>
#include <math.h>
#include <float.h>
#include <stdint.h>

#define HID 128
#define MAX_NODES 50000
#define MAX_EDGES 800000

// ------------------------- scratch (static, no allocs) -------------------------
__device__ float   g_A[MAX_NODES * HID];       // z @ Wd (fp32)
__device__ __half2 g_Bh[MAX_NODES * (HID/2)];  // z @ Ws (fp16 storage)
__device__ __half2 g_aggh[MAX_NODES * (HID/2)];// agg result (fp16 storage)
__device__ int     g_deg[MAX_NODES];
__device__ int     g_off[MAX_NODES + 1];
__device__ int     g_cur[MAX_NODES];
__device__ int     g_csr[MAX_EDGES];

// ------------------------- fp16 mma helpers (sm_80+ baseline PTX only) -------------------------
__device__ __forceinline__ uint32_t h2u(__half2 h) {
    return *(const uint32_t*)&h;
}

__device__ __forceinline__ uint32_t f2h2(float a, float b) {
    const __half2 h = __floats2half2_rn(a, b);
    return *(const uint32_t*)&h;
}

__device__ __forceinline__ void mma_f16(float* c, const uint32_t* a, uint32_t b0, uint32_t b1) {
    asm volatile(
        "mma.sync.aligned.m16n8k16.row.col.f32.f16.f16.f32 "
        "{%0,%1,%2,%3}, {%4,%5,%6,%7}, {%8,%9}, {%0,%1,%2,%3};"
        : "+f"(c[0]), "+f"(c[1]), "+f"(c[2]), "+f"(c[3])
        : "r"(a[0]), "r"(a[1]), "r"(a[2]), "r"(a[3]), "r"(b0), "r"(b1));
}

// tiling: CTA = 256 thr = 8 warps (4M x 2N), tile 128(M) x 128(N)
// pitches in half2 (uint32) units; pitch%32==4 with pitch=4*odd -> frag loads conflict-free
#define PA2C 36    // chunk-A pitch   (36 = 4*9)
#define PA2F 68    // full-A / hid pitch (68 = 4*17)
#define PB2  36    // B pitch, [n][k] transposed

// ------------------------- compute core: 4 k16-steps over one 64-K chunk -------------------------
__device__ __forceinline__ void mma_chunk_f16(
    float acc[2][8][4], const uint32_t* __restrict__ Asm, int apitch2, int acol2,
    const uint32_t* __restrict__ Bsm, int bcol2, int wm, int wn, int g, int tg)
{
#pragma unroll
    for (int kk2 = 0; kk2 < 32; kk2 += 8) {   // 8 half2 = 16 K per step
        uint32_t a[2][4];
#pragma unroll
        for (int mt = 0; mt < 2; mt++) {
            const uint32_t* ap = Asm + (wm + mt * 16 + g) * apitch2 + acol2 + kk2 + tg;
            a[mt][0] = ap[0];
            a[mt][1] = ap[8 * apitch2];
            a[mt][2] = ap[4];
            a[mt][3] = ap[8 * apitch2 + 4];
        }
#pragma unroll
        for (int nt = 0; nt < 8; nt++) {
            const uint32_t* bp = Bsm + (wn + nt * 8 + g) * PB2 + bcol2 + kk2 + tg;
            const uint32_t b0 = bp[0];
            const uint32_t b1 = bp[4];
            mma_f16(acc[0][nt], a[0], b0, b1);
            mma_f16(acc[1][nt], a[1], b0, b1);
        }
    }
}

// B-fill: W rows [kw, kw+64) of [128][HID] f32 -> Bs[n][k2] half2 (transposed, k-pairs)
__device__ __forceinline__ void fill_B(
    uint32_t* __restrict__ Bs, const float* __restrict__ W, int kw, int tid)
{
#pragma unroll
    for (int it = 0; it < 16; it++) {
        const int i = it * 256 + tid;
        const int n  = i & 127;
        const int k2 = i >> 7;
        const float w0 = W[(size_t)(kw + 2 * k2) * HID + n];
        const float w1 = W[(size_t)(kw + 2 * k2 + 1) * HID + n];
        Bs[n * PB2 + k2] = f2h2(w0, w1);
    }
}

// ------------------------- gemm2: load z tile once, emit g_A = z@Wd (fp32), g_Bh = z@Ws (fp16) -------------------------
// smem (half2 units): AsF [128][PA2F] @0 (8704), Bs [128][PB2] @8704 (4608) -> 53248 B
#define GEMM2_SMEM (53248)

__global__ __launch_bounds__(256, 2) void gemm2_kernel(
    const float* __restrict__ z, const float* __restrict__ Wm, int M)
{
    extern __shared__ uint32_t sm[];
    uint32_t* As = sm;                  // [128][PA2F] full K=128 (half2)
    uint32_t* Bs = sm + 128 * PA2F;     // [128][PB2] one K-chunk transposed

    const int tid  = threadIdx.x;
    const int wid  = tid >> 5;
    const int lane = tid & 31;
    const int g    = lane >> 2;
    const int tg   = lane & 3;
    const int wm   = (wid & 3) << 5;
    const int wn   = (wid >> 2) << 6;
    const int rowBase = blockIdx.x * 128;

    // load full A tile (128 x 128) as fp16
#pragma unroll
    for (int it = 0; it < 16; it++) {
        const int i = it * 256 + tid;
        const int row = i >> 5;
        const int c4  = (i & 31) << 2;
        const int gr = rowBase + row;
        float4 v = make_float4(0.f, 0.f, 0.f, 0.f);
        if (gr < M) v = *(const float4*)(z + (size_t)gr * HID + c4);
        uint2 t;
        t.x = f2h2(v.x, v.y);
        t.y = f2h2(v.z, v.w);
        *(uint2*)(As + row * PA2F + (c4 >> 1)) = t;
    }

    for (int w = 0; w < 2; w++) {
        const float* W = Wm + (size_t)w * 128 * HID;
        float acc[2][8][4];
#pragma unroll
        for (int mt = 0; mt < 2; mt++)
#pragma unroll
            for (int nt = 0; nt < 8; nt++)
#pragma unroll
                for (int i = 0; i < 4; i++) acc[mt][nt][i] = 0.f;

        for (int chunk = 0; chunk < 2; chunk++) {
            fill_B(Bs, W, chunk * 64, tid);
            __syncthreads();
            mma_chunk_f16(acc, As, PA2F, chunk * 32, Bs, 0, wm, wn, g, tg);
            __syncthreads();
        }

#pragma unroll
        for (int mt = 0; mt < 2; mt++) {
            const int r0 = rowBase + wm + mt * 16 + g;
            const int r1 = r0 + 8;
#pragma unroll
            for (int nt = 0; nt < 8; nt++) {
                const int cb = wn + nt * 8 + tg * 2;
                if (w == 0) {
                    if (r0 < M) *(float2*)(g_A + (size_t)r0 * HID + cb) =
                        make_float2(acc[mt][nt][0], acc[mt][nt][1]);
                    if (r1 < M) *(float2*)(g_A + (size_t)r1 * HID + cb) =
                        make_float2(acc[mt][nt][2], acc[mt][nt][3]);
                } else {
                    if (r0 < M) g_Bh[(size_t)r0 * (HID/2) + (cb >> 1)] =
                        __floats2half2_rn(acc[mt][nt][0], acc[mt][nt][1]);
                    if (r1 < M) g_Bh[(size_t)r1 * (HID/2) + (cb >> 1)] =
                        __floats2half2_rn(acc[mt][nt][2], acc[mt][nt][3]);
                }
            }
        }
    }
}

// ------------------------- fused MLP: hidden = relu([z|agg]@W1 + b1); out = hidden@W2 + b2 -------------------------
// smem (half2 units): As1 [128][PA2C] @0 (4608), Bs1 @4608 (4608),
//                     hid [128][PA2F] @0 (8704, clobbers As1 + Bs1 head), Bs2 @9216 (4608)
//                     -> 13824 h2 = 55296 B
#define FUSED_SMEM (55296)

__global__ __launch_bounds__(256, 2) void fused_mlp_kernel(
    const float* __restrict__ z, const float* __restrict__ W1,
    const float* __restrict__ b1, const float* __restrict__ W2,
    const float* __restrict__ b2, float* __restrict__ out, int M)
{
    extern __shared__ uint32_t sm[];
    uint32_t* As1 = sm;                 // [128][PA2C]
    uint32_t* Bs1 = sm + 4608;          // [128][PB2]
    uint32_t* hid = sm;                 // [128][PA2F] (clobbers As1/Bs1)
    uint32_t* Bs2 = sm + 9216;          // [128][PB2]

    const int tid  = threadIdx.x;
    const int wid  = tid >> 5;
    const int lane = tid & 31;
    const int g    = lane >> 2;
    const int tg   = lane & 3;
    const int wm   = (wid & 3) << 5;
    const int wn   = (wid >> 2) << 6;
    const int rowBase = blockIdx.x * 128;

    float acc[2][8][4];
#pragma unroll
    for (int mt = 0; mt < 2; mt++)
#pragma unroll
        for (int nt = 0; nt < 8; nt++)
#pragma unroll
            for (int i = 0; i < 4; i++) acc[mt][nt][i] = 0.f;

    // ---- stage 1: K=256 over [z | agg] with W1[256][128] ----
    for (int chunk = 0; chunk < 4; chunk++) {
        const int kloc = (chunk & 1) * 64;
#pragma unroll
        for (int it = 0; it < 8; it++) {
            const int i = it * 256 + tid;
            const int row = i >> 4;
            const int c4  = (i & 15) << 2;
            const int gr = rowBase + row;
            uint2 t = make_uint2(0u, 0u);
            if (chunk < 2) {
                if (gr < M) {
                    const float4 v = *(const float4*)(z + (size_t)gr * HID + kloc + c4);
                    t.x = f2h2(v.x, v.y);
                    t.y = f2h2(v.z, v.w);
                }
            } else {
                // agg already fp16 -> straight copy, no conversion
                if (gr < M)
                    t = *(const uint2*)(g_aggh + (size_t)gr * (HID/2) + ((kloc + c4) >> 1));
            }
            *(uint2*)(As1 + row * PA2C + (c4 >> 1)) = t;
        }
        fill_B(Bs1, W1, chunk * 64, tid);
        __syncthreads();
        mma_chunk_f16(acc, As1, PA2C, 0, Bs1, 0, wm, wn, g, tg);
        __syncthreads();
    }

    // ---- stage-1 epilogue: hid = fp16(relu(acc + b1)) ----
#pragma unroll
    for (int mt = 0; mt < 2; mt++) {
        const int lr0 = wm + mt * 16 + g;
        const int lr1 = lr0 + 8;
#pragma unroll
        for (int nt = 0; nt < 8; nt++) {
            const int cb = wn + nt * 8 + tg * 2;
            const float bb0 = b1[cb], bb1 = b1[cb + 1];
            hid[lr0 * PA2F + (cb >> 1)] =
                f2h2(fmaxf(acc[mt][nt][0] + bb0, 0.f), fmaxf(acc[mt][nt][1] + bb1, 0.f));
            hid[lr1 * PA2F + (cb >> 1)] =
                f2h2(fmaxf(acc[mt][nt][2] + bb0, 0.f), fmaxf(acc[mt][nt][3] + bb1, 0.f));
        }
    }
    __syncthreads();

    // ---- stage 2: out = hid @ W2 + b2 ----
#pragma unroll
    for (int mt = 0; mt < 2; mt++)
#pragma unroll
        for (int nt = 0; nt < 8; nt++)
#pragma unroll
            for (int i = 0; i < 4; i++) acc[mt][nt][i] = 0.f;

    for (int chunk = 0; chunk < 2; chunk++) {
        fill_B(Bs2, W2, chunk * 64, tid);
        __syncthreads();
        mma_chunk_f16(acc, hid, PA2F, chunk * 32, Bs2, 0, wm, wn, g, tg);
        __syncthreads();
    }

#pragma unroll
    for (int mt = 0; mt < 2; mt++) {
        const int r0 = rowBase + wm + mt * 16 + g;
        const int r1 = r0 + 8;
#pragma unroll
        for (int nt = 0; nt < 8; nt++) {
            const int cb = wn + nt * 8 + tg * 2;
            const float bb0 = b2[cb], bb1 = b2[cb + 1];
            if (r0 < M) *(float2*)(out + (size_t)r0 * HID + cb) =
                make_float2(acc[mt][nt][0] + bb0, acc[mt][nt][1] + bb1);
            if (r1 < M) *(float2*)(out + (size_t)r1 * HID + cb) =
                make_float2(acc[mt][nt][2] + bb0, acc[mt][nt][3] + bb1);
        }
    }
}

// ------------------------- CSR build -------------------------
__global__ void zero_deg_kernel(int nNodes)
{
    int i = blockIdx.x * blockDim.x + threadIdx.x;
    if (i < nNodes) g_deg[i] = 0;
}

__global__ void deg_kernel(const int* __restrict__ dst, int nE)
{
    int e = blockIdx.x * blockDim.x + threadIdx.x;
    if (e < nE) atomicAdd(&g_deg[dst[e]], 1);
}

__global__ __launch_bounds__(1024) void scan_kernel(int nNodes)
{
    __shared__ int warpPre[32];
    __shared__ int s_carry;
    const int tid = threadIdx.x;
    const int lane = tid & 31;
    const int wid = tid >> 5;
    if (tid == 0) s_carry = 0;
    __syncthreads();
    const int nChunks = (nNodes + 1023) >> 10;
    for (int c = 0; c < nChunks; c++) {
        const int i = (c << 10) + tid;
        const int v = (i < nNodes) ? g_deg[i] : 0;
        int incl = v;
#pragma unroll
        for (int o = 1; o < 32; o <<= 1) {
            int t = __shfl_up_sync(0xffffffffu, incl, o);
            if (lane >= o) incl += t;
        }
        if (lane == 31) warpPre[wid] = incl;
        __syncthreads();
        if (wid == 0) {
            int ws = warpPre[lane];
            int wincl = ws;
#pragma unroll
            for (int o = 1; o < 32; o <<= 1) {
                int t = __shfl_up_sync(0xffffffffu, wincl, o);
                if (lane >= o) wincl += t;
            }
            warpPre[lane] = wincl - ws;
        }
        __syncthreads();
        const int excl = s_carry + warpPre[wid] + incl - v;
        if (i < nNodes) { g_off[i] = excl; g_cur[i] = excl; }
        __syncthreads();
        if (tid == 1023) s_carry = excl + v;
        __syncthreads();
    }
    if (tid == 0) g_off[nNodes] = s_carry;
}

__global__ void scatter_kernel(const int* __restrict__ dst, int nE)
{
    int e = blockIdx.x * blockDim.x + threadIdx.x;
    if (e < nE) {
        int p = atomicAdd(&g_cur[dst[e]], 1);
        g_csr[p] = e;
    }
}

// ------------------------- per-node gather-max (fp16 g_B rows, edge loop unrolled 2x) -------------------------
__global__ __launch_bounds__(256) void agg_kernel(
    const int* __restrict__ src, const float* __restrict__ ew,
    const float* __restrict__ Wm, const float* __restrict__ bm,
    int nNodes)
{
    const int warpId = (blockIdx.x * blockDim.x + threadIdx.x) >> 5;
    const int lane = threadIdx.x & 31;
    if (warpId >= nNodes) return;
    const int n = warpId;
    const float4 ww4 = *(const float4*)(Wm + 256 * HID + lane * 4);
    const int s0 = g_off[n], s1 = g_off[n + 1];
    float4 m = make_float4(-FLT_MAX, -FLT_MAX, -FLT_MAX, -FLT_MAX);
    for (int base = s0; base < s1; base += 32) {
        const int idx = base + lane;
        int sv = 0; float wv = 0.f;
        if (idx < s1) {
            const int e = g_csr[idx];
            sv = src[e];
            wv = ew[e];
        }
        const int cnt = min(32, s1 - base);
        int j = 0;
        for (; j + 1 < cnt; j += 2) {
            const int   sj0 = __shfl_sync(0xffffffffu, sv, j);
            const float wj0 = __shfl_sync(0xffffffffu, wv, j);
            const int   sj1 = __shfl_sync(0xffffffffu, sv, j + 1);
            const float wj1 = __shfl_sync(0xffffffffu, wv, j + 1);
            const uint2 h0 = *(const uint2*)(g_Bh + (size_t)sj0 * (HID/2) + lane * 2);
            const uint2 h1 = *(const uint2*)(g_Bh + (size_t)sj1 * (HID/2) + lane * 2);
            const float2 b0a = __half22float2(*(const __half2*)&h0.x);
            const float2 b0b = __half22float2(*(const __half2*)&h0.y);
            const float2 b1a = __half22float2(*(const __half2*)&h1.x);
            const float2 b1b = __half22float2(*(const __half2*)&h1.y);
            m.x = fmaxf(m.x, fmaf(wj0, ww4.x, b0a.x));
            m.y = fmaxf(m.y, fmaf(wj0, ww4.y, b0a.y));
            m.z = fmaxf(m.z, fmaf(wj0, ww4.z, b0b.x));
            m.w = fmaxf(m.w, fmaf(wj0, ww4.w, b0b.y));
            m.x = fmaxf(m.x, fmaf(wj1, ww4.x, b1a.x));
            m.y = fmaxf(m.y, fmaf(wj1, ww4.y, b1a.y));
            m.z = fmaxf(m.z, fmaf(wj1, ww4.z, b1b.x));
            m.w = fmaxf(m.w, fmaf(wj1, ww4.w, b1b.y));
        }
        if (j < cnt) {
            const int   sj = __shfl_sync(0xffffffffu, sv, j);
            const float wj = __shfl_sync(0xffffffffu, wv, j);
            const uint2 h0 = *(const uint2*)(g_Bh + (size_t)sj * (HID/2) + lane * 2);
            const float2 b0a = __half22float2(*(const __half2*)&h0.x);
            const float2 b0b = __half22float2(*(const __half2*)&h0.y);
            m.x = fmaxf(m.x, fmaf(wj, ww4.x, b0a.x));
            m.y = fmaxf(m.y, fmaf(wj, ww4.y, b0a.y));
            m.z = fmaxf(m.z, fmaf(wj, ww4.z, b0b.x));
            m.w = fmaxf(m.w, fmaf(wj, ww4.w, b0b.y));
        }
    }
    uint2 o;
    if (s1 > s0) {
        const float4 a4 = *(const float4*)(g_A + (size_t)n * HID + lane * 4);
        const float4 bm4 = *(const float4*)(bm + lane * 4);
        const __half2 o01 = __floats2half2_rn(a4.x + bm4.x + m.x, a4.y + bm4.y + m.y);
        const __half2 o23 = __floats2half2_rn(a4.z + bm4.z + m.z, a4.w + bm4.w + m.w);
        o.x = *(const uint32_t*)&o01;
        o.y = *(const uint32_t*)&o23;
    } else {
        o.x = 0u; o.y = 0u;
    }
    *(uint2*)(g_aggh + (size_t)n * (HID/2) + lane * 2) = o;
}

// ------------------------- launch -------------------------
extern "C" void kernel_launch(void* const* d_in, const int* in_sizes, int n_in,
                              void* d_out, int out_size)
{
    const float* z   = (const float*)d_in[0];
    const float* ew  = (const float*)d_in[1];
    const int*   esrc= (const int*)d_in[2];
    const int*   edst= (const int*)d_in[3];
    const float* Wm  = (const float*)d_in[4];
    const float* bm  = (const float*)d_in[5];
    const float* W1  = (const float*)d_in[6];
    const float* b1  = (const float*)d_in[7];
    const float* W2  = (const float*)d_in[8];
    const float* b2  = (const float*)d_in[9];
    float* out = (float*)d_out;

    const int nNodes = in_sizes[0] / HID;
    const int nEdges = in_sizes[1];

    cudaFuncSetAttribute(gemm2_kernel, cudaFuncAttributeMaxDynamicSharedMemorySize, GEMM2_SMEM);
    cudaFuncSetAttribute(fused_mlp_kernel, cudaFuncAttributeMaxDynamicSharedMemorySize, FUSED_SMEM);

    // lazily-created side stream + fork/join events (host-side objects, no device mem)
    static cudaStream_t s_side = nullptr;
    static cudaEvent_t  s_evFork = nullptr, s_evCsr = nullptr;
    if (!s_side) {
        cudaStreamCreateWithFlags(&s_side, cudaStreamNonBlocking);
        cudaEventCreateWithFlags(&s_evFork, cudaEventDisableTiming);
        cudaEventCreateWithFlags(&s_evCsr, cudaEventDisableTiming);
    }

    const int gemmGrid = (nNodes + 127) / 128;
    const int edgeGrid = (nEdges + 255) / 256;
    const int nodeGrid = (nNodes + 255) / 256;
    const int aggGrid  = (nNodes + 7) / 8;

    // fork: CSR build (edge-only inputs) runs concurrently with gemm2 (z-only inputs)
    cudaEventRecord(s_evFork, 0);
    cudaStreamWaitEvent(s_side, s_evFork, 0);

    // side stream: CSR build
    zero_deg_kernel<<<nodeGrid, 256, 0, s_side>>>(nNodes);
    deg_kernel<<<edgeGrid, 256, 0, s_side>>>(edst, nEdges);
    scan_kernel<<<1, 1024, 0, s_side>>>(nNodes);
    scatter_kernel<<<edgeGrid, 256, 0, s_side>>>(edst, nEdges);
    cudaEventRecord(s_evCsr, s_side);

    // main stream: shared-A dual projection g_A = z@Wd (fp32), g_Bh = z@Ws (fp16)
    gemm2_kernel<<<gemmGrid, 256, GEMM2_SMEM>>>(z, Wm, nNodes);

    // join: agg needs both CSR and g_A/g_Bh
    cudaStreamWaitEvent(0, s_evCsr, 0);

    // segment max (gather form, fp16 rows)
    agg_kernel<<<aggGrid, 256>>>(esrc, ew, Wm, bm, nNodes);

    // fused: hidden = relu([z|agg]@W1 + b1); out = hidden@W2 + b2
    fused_mlp_kernel<<<gemmGrid, 256, FUSED_SMEM>>>(z, W1, b1, W2, b2, out, nNodes);
}

// round 14
// speedup vs baseline: 1.8492x; 1.1976x over previous
#include <cuda_runtime.h>
#include <cuda_fp16.h>
#include <math.h>
#include <float.h>
#include <stdint.h>

#define HID 128
#define MAX_NODES 50000
#define MAX_EDGES 800000

// ------------------------- scratch (static, no allocs) -------------------------
__device__ float   g_A[MAX_NODES * HID];       // z @ Wd (fp32)
__device__ __half2 g_Bh[MAX_NODES * (HID/2)];  // z @ Ws (fp16 storage)
__device__ __half2 g_aggh[MAX_NODES * (HID/2)];// agg result (fp16 storage)
__device__ int     g_deg[MAX_NODES];
__device__ int     g_off[MAX_NODES + 1];
__device__ int     g_cur[MAX_NODES];
__device__ int     g_csr[MAX_EDGES];

// pre-transposed fp16 weights: [n][k] layout (B-tile ready, no per-tile transpose/convert)
__device__ __align__(16) __half g_WdT[128 * 128];
__device__ __align__(16) __half g_WsT[128 * 128];
__device__ __align__(16) __half g_W1T[128 * 256];
__device__ __align__(16) __half g_W2T[128 * 128];

// ------------------------- helpers (sm_80+ baseline PTX only) -------------------------
__device__ __forceinline__ uint32_t smem_u32(const void* p) {
    uint32_t a;
    asm("{ .reg .u64 t; cvta.to.shared.u64 t, %1; cvt.u32.u64 %0, t; }" : "=r"(a) : "l"(p));
    return a;
}

__device__ __forceinline__ void cp16(uint32_t dst, const void* src) {
    asm volatile("cp.async.cg.shared.global [%0], [%1], 16;" :: "r"(dst), "l"(src));
}
#define CP_COMMIT()  asm volatile("cp.async.commit_group;" ::: "memory")
#define CP_WAIT1()   asm volatile("cp.async.wait_group 1;" ::: "memory")
#define CP_WAIT0()   asm volatile("cp.async.wait_group 0;" ::: "memory")

__device__ __forceinline__ uint32_t f2h2(float a, float b) {
    const __half2 h = __floats2half2_rn(a, b);
    return *(const uint32_t*)&h;
}

__device__ __forceinline__ void mma_f16(float* c, const uint32_t* a, uint32_t b0, uint32_t b1) {
    asm volatile(
        "mma.sync.aligned.m16n8k16.row.col.f32.f16.f16.f32 "
        "{%0,%1,%2,%3}, {%4,%5,%6,%7}, {%8,%9}, {%0,%1,%2,%3};"
        : "+f"(c[0]), "+f"(c[1]), "+f"(c[2]), "+f"(c[3])
        : "r"(a[0]), "r"(a[1]), "r"(a[2]), "r"(a[3]), "r"(b0), "r"(b1));
}

// tiling: CTA = 256 thr = 8 warps (4M x 2N), tile 128(M) x 128(N)
// pitches in half2 (uint32) units; pitch=4*odd -> frag loads conflict-free
#define PA2C 36    // chunk-A pitch
#define PA2F 68    // full-A / hid pitch
#define PB2  36    // B pitch, [n][k] transposed

// ------------------------- compute core: 4 k16-steps over one 64-K chunk -------------------------
__device__ __forceinline__ void mma_chunk_f16(
    float acc[2][8][4], const uint32_t* __restrict__ Asm, int apitch2, int acol2,
    const uint32_t* __restrict__ Bsm, int wm, int wn, int g, int tg)
{
#pragma unroll
    for (int kk2 = 0; kk2 < 32; kk2 += 8) {   // 8 half2 = 16 K per step
        uint32_t a[2][4];
#pragma unroll
        for (int mt = 0; mt < 2; mt++) {
            const uint32_t* ap = Asm + (wm + mt * 16 + g) * apitch2 + acol2 + kk2 + tg;
            a[mt][0] = ap[0];
            a[mt][1] = ap[8 * apitch2];
            a[mt][2] = ap[4];
            a[mt][3] = ap[8 * apitch2 + 4];
        }
#pragma unroll
        for (int nt = 0; nt < 8; nt++) {
            const uint32_t* bp = Bsm + (wn + nt * 8 + g) * PB2 + kk2 + tg;
            const uint32_t b0 = bp[0];
            const uint32_t b1 = bp[4];
            mma_f16(acc[0][nt], a[0], b0, b1);
            mma_f16(acc[1][nt], a[1], b0, b1);
        }
    }
}

// async B fill: WT[n][kw..kw+64) fp16 -> Bs[n][k2] (row = 128B, 8x16B chunks)
__device__ __forceinline__ void cp_fill_B(
    uint32_t dstBase, const __half* __restrict__ WT, int kw, int kstride, int tid)
{
#pragma unroll
    for (int it = 0; it < 4; it++) {
        const int i = it * 256 + tid;     // 0..1023
        const int n = i >> 3;             // row 0..127
        const int c = i & 7;              // 16B chunk
        cp16(dstBase + n * (PB2 * 4) + c * 16, WT + (size_t)n * kstride + kw + c * 8);
    }
}

// ------------------------- weight prep: transpose + fp16 convert (once per launch) -------------------------
__global__ void prep_weights(const float* __restrict__ Wm, const float* __restrict__ W1,
                             const float* __restrict__ W2)
{
    const int i = blockIdx.x * blockDim.x + threadIdx.x;
    if (i < 128 * 256) {
        const int n = i >> 8, k = i & 255;
        g_W1T[n * 256 + k] = __float2half_rn(W1[(size_t)k * 128 + n]);
    }
    if (i < 128 * 128) {
        const int n = i >> 7, k = i & 127;
        g_WdT[n * 128 + k] = __float2half_rn(Wm[(size_t)k * 128 + n]);
        g_WsT[n * 128 + k] = __float2half_rn(Wm[(size_t)(128 + k) * 128 + n]);
        g_W2T[n * 128 + k] = __float2half_rn(W2[(size_t)k * 128 + n]);
    }
}

// ------------------------- gemm2: load z tile once, emit g_A = z@Wd (fp32), g_Bh = z@Ws (fp16) -------------------------
// smem (words): As [128][PA2F] (8704) + B0 (4608) + B1 (4608) = 17920 w = 71680 B -> 2 CTA/SM
#define GEMM2_SMEM (71680)

__global__ __launch_bounds__(256, 2) void gemm2_kernel(const float* __restrict__ z, int M)
{
    extern __shared__ uint32_t sm[];
    uint32_t* As = sm;                       // [128][PA2F] full K=128 (half2)
    uint32_t* Bbuf[2] = { sm + 128 * PA2F, sm + 128 * PA2F + 128 * PB2 };
    const uint32_t bAddr[2] = { smem_u32(Bbuf[0]), smem_u32(Bbuf[1]) };

    const int tid  = threadIdx.x;
    const int wid  = tid >> 5;
    const int lane = tid & 31;
    const int g    = lane >> 2;
    const int tg   = lane & 3;
    const int wm   = (wid & 3) << 5;
    const int wn   = (wid >> 2) << 6;
    const int rowBase = blockIdx.x * 128;

    // kick off B pipeline: step0 = (WdT, kw=0)
    cp_fill_B(bAddr[0], g_WdT, 0, 128, tid);
    CP_COMMIT();

    // load full A tile (128 x 128) as fp16 (overlaps the cp.async above)
#pragma unroll
    for (int it = 0; it < 16; it++) {
        const int i = it * 256 + tid;
        const int row = i >> 5;
        const int c4  = (i & 31) << 2;
        const int gr = rowBase + row;
        float4 v = make_float4(0.f, 0.f, 0.f, 0.f);
        if (gr < M) v = *(const float4*)(z + (size_t)gr * HID + c4);
        uint2 t;
        t.x = f2h2(v.x, v.y);
        t.y = f2h2(v.z, v.w);
        *(uint2*)(As + row * PA2F + (c4 >> 1)) = t;
    }

    // step table: 0:(WdT,0) 1:(WdT,64) 2:(WsT,0) 3:(WsT,64)
    int cur = 0;
    for (int w = 0; w < 2; w++) {
        float acc[2][8][4];
#pragma unroll
        for (int mt = 0; mt < 2; mt++)
#pragma unroll
            for (int nt = 0; nt < 8; nt++)
#pragma unroll
                for (int i = 0; i < 4; i++) acc[mt][nt][i] = 0.f;

        for (int chunk = 0; chunk < 2; chunk++) {
            const int step = w * 2 + chunk;
            if (step < 3) {
                const __half* nWT = (step == 0) ? g_WdT : g_WsT;
                const int nkw = (step == 1) ? 0 : 64;
                cp_fill_B(bAddr[cur ^ 1], nWT, nkw, 128, tid);
                CP_COMMIT();
                CP_WAIT1();
            } else {
                CP_WAIT0();
            }
            __syncthreads();
            mma_chunk_f16(acc, As, PA2F, chunk * 32, Bbuf[cur], wm, wn, g, tg);
            __syncthreads();
            cur ^= 1;
        }

#pragma unroll
        for (int mt = 0; mt < 2; mt++) {
            const int r0 = rowBase + wm + mt * 16 + g;
            const int r1 = r0 + 8;
#pragma unroll
            for (int nt = 0; nt < 8; nt++) {
                const int cb = wn + nt * 8 + tg * 2;
                if (w == 0) {
                    if (r0 < M) *(float2*)(g_A + (size_t)r0 * HID + cb) =
                        make_float2(acc[mt][nt][0], acc[mt][nt][1]);
                    if (r1 < M) *(float2*)(g_A + (size_t)r1 * HID + cb) =
                        make_float2(acc[mt][nt][2], acc[mt][nt][3]);
                } else {
                    if (r0 < M) g_Bh[(size_t)r0 * (HID/2) + (cb >> 1)] =
                        __floats2half2_rn(acc[mt][nt][0], acc[mt][nt][1]);
                    if (r1 < M) g_Bh[(size_t)r1 * (HID/2) + (cb >> 1)] =
                        __floats2half2_rn(acc[mt][nt][2], acc[mt][nt][3]);
                }
            }
        }
    }
}

// ------------------------- fused MLP: hidden = relu([z|agg]@W1 + b1); out = hidden@W2 + b2 -------------------------
// smem (words): As1 [128][PA2C] @0 (4608), B0 @4608 (4608), B1 @9216 (4608), hid [128][PA2F] @13824 (8704)
//               total 22528 w = 90112 B -> 2 CTA/SM
#define FUSED_SMEM (90112)

__global__ __launch_bounds__(256, 2) void fused_mlp_kernel(
    const float* __restrict__ z, const float* __restrict__ b1,
    const float* __restrict__ b2, float* __restrict__ out, int M)
{
    extern __shared__ uint32_t sm[];
    uint32_t* As1 = sm;                      // [128][PA2C]
    uint32_t* Bbuf[2] = { sm + 4608, sm + 9216 };
    uint32_t* hid = sm + 13824;              // [128][PA2F]
    const uint32_t bAddr[2] = { smem_u32(Bbuf[0]), smem_u32(Bbuf[1]) };

    const int tid  = threadIdx.x;
    const int wid  = tid >> 5;
    const int lane = tid & 31;
    const int g    = lane >> 2;
    const int tg   = lane & 3;
    const int wm   = (wid & 3) << 5;
    const int wn   = (wid >> 2) << 6;
    const int rowBase = blockIdx.x * 128;

    // kick off B pipeline: step0 = (W1T, kw=0)
    cp_fill_B(bAddr[0], g_W1T, 0, 256, tid);
    CP_COMMIT();

    float acc[2][8][4];
#pragma unroll
    for (int mt = 0; mt < 2; mt++)
#pragma unroll
        for (int nt = 0; nt < 8; nt++)
#pragma unroll
            for (int i = 0; i < 4; i++) acc[mt][nt][i] = 0.f;

    int cur = 0;
    // ---- stage 1: K=256 over [z | agg] with W1 ----
    // steps 0..3: (W1T, step*64); steps 4..5: (W2T, (step-4)*64)
    for (int chunk = 0; chunk < 4; chunk++) {
        const int kloc = (chunk & 1) * 64;
        // A-chunk fill (sync; overlaps in-flight cp.async groups)
#pragma unroll
        for (int it = 0; it < 8; it++) {
            const int i = it * 256 + tid;
            const int row = i >> 4;
            const int c4  = (i & 15) << 2;
            const int gr = rowBase + row;
            uint2 t = make_uint2(0u, 0u);
            if (chunk < 2) {
                if (gr < M) {
                    const float4 v = *(const float4*)(z + (size_t)gr * HID + kloc + c4);
                    t.x = f2h2(v.x, v.y);
                    t.y = f2h2(v.z, v.w);
                }
            } else {
                if (gr < M)
                    t = *(const uint2*)(g_aggh + (size_t)gr * (HID/2) + ((kloc + c4) >> 1));
            }
            *(uint2*)(As1 + row * PA2C + (c4 >> 1)) = t;
        }
        // prefetch next step
        if (chunk < 3) {
            cp_fill_B(bAddr[cur ^ 1], g_W1T, (chunk + 1) * 64, 256, tid);
        } else {
            cp_fill_B(bAddr[cur ^ 1], g_W2T, 0, 128, tid);
        }
        CP_COMMIT();
        CP_WAIT1();
        __syncthreads();
        mma_chunk_f16(acc, As1, PA2C, 0, Bbuf[cur], wm, wn, g, tg);
        __syncthreads();
        cur ^= 1;
    }

    // ---- stage-1 epilogue: hid = fp16(relu(acc + b1)) ----
#pragma unroll
    for (int mt = 0; mt < 2; mt++) {
        const int lr0 = wm + mt * 16 + g;
        const int lr1 = lr0 + 8;
#pragma unroll
        for (int nt = 0; nt < 8; nt++) {
            const int cb = wn + nt * 8 + tg * 2;
            const float bb0 = b1[cb], bb1 = b1[cb + 1];
            hid[lr0 * PA2F + (cb >> 1)] =
                f2h2(fmaxf(acc[mt][nt][0] + bb0, 0.f), fmaxf(acc[mt][nt][1] + bb1, 0.f));
            hid[lr1 * PA2F + (cb >> 1)] =
                f2h2(fmaxf(acc[mt][nt][2] + bb0, 0.f), fmaxf(acc[mt][nt][3] + bb1, 0.f));
        }
    }
    __syncthreads();

    // ---- stage 2: out = hid @ W2 + b2 ----
#pragma unroll
    for (int mt = 0; mt < 2; mt++)
#pragma unroll
        for (int nt = 0; nt < 8; nt++)
#pragma unroll
            for (int i = 0; i < 4; i++) acc[mt][nt][i] = 0.f;

    for (int chunk = 0; chunk < 2; chunk++) {
        if (chunk == 0) {
            cp_fill_B(bAddr[cur ^ 1], g_W2T, 64, 128, tid);
            CP_COMMIT();
            CP_WAIT1();
        } else {
            CP_WAIT0();
        }
        __syncthreads();
        mma_chunk_f16(acc, hid, PA2F, chunk * 32, Bbuf[cur], wm, wn, g, tg);
        __syncthreads();
        cur ^= 1;
    }

#pragma unroll
    for (int mt = 0; mt < 2; mt++) {
        const int r0 = rowBase + wm + mt * 16 + g;
        const int r1 = r0 + 8;
#pragma unroll
        for (int nt = 0; nt < 8; nt++) {
            const int cb = wn + nt * 8 + tg * 2;
            const float bb0 = b2[cb], bb1 = b2[cb + 1];
            if (r0 < M) *(float2*)(out + (size_t)r0 * HID + cb) =
                make_float2(acc[mt][nt][0] + bb0, acc[mt][nt][1] + bb1);
            if (r1 < M) *(float2*)(out + (size_t)r1 * HID + cb) =
                make_float2(acc[mt][nt][2] + bb0, acc[mt][nt][3] + bb1);
        }
    }
}

// ------------------------- CSR build -------------------------
__global__ void zero_deg_kernel(int nNodes)
{
    int i = blockIdx.x * blockDim.x + threadIdx.x;
    if (i < nNodes) g_deg[i] = 0;
}

__global__ void deg_kernel(const int* __restrict__ dst, int nE)
{
    int e = blockIdx.x * blockDim.x + threadIdx.x;
    if (e < nE) atomicAdd(&g_deg[dst[e]], 1);
}

__global__ __launch_bounds__(1024) void scan_kernel(int nNodes)
{
    __shared__ int warpPre[32];
    __shared__ int s_carry;
    const int tid = threadIdx.x;
    const int lane = tid & 31;
    const int wid = tid >> 5;
    if (tid == 0) s_carry = 0;
    __syncthreads();
    const int nChunks = (nNodes + 1023) >> 10;
    for (int c = 0; c < nChunks; c++) {
        const int i = (c << 10) + tid;
        const int v = (i < nNodes) ? g_deg[i] : 0;
        int incl = v;
#pragma unroll
        for (int o = 1; o < 32; o <<= 1) {
            int t = __shfl_up_sync(0xffffffffu, incl, o);
            if (lane >= o) incl += t;
        }
        if (lane == 31) warpPre[wid] = incl;
        __syncthreads();
        if (wid == 0) {
            int ws = warpPre[lane];
            int wincl = ws;
#pragma unroll
            for (int o = 1; o < 32; o <<= 1) {
                int t = __shfl_up_sync(0xffffffffu, wincl, o);
                if (lane >= o) wincl += t;
            }
            warpPre[lane] = wincl - ws;
        }
        __syncthreads();
        const int excl = s_carry + warpPre[wid] + incl - v;
        if (i < nNodes) { g_off[i] = excl; g_cur[i] = excl; }
        __syncthreads();
        if (tid == 1023) s_carry = excl + v;
        __syncthreads();
    }
    if (tid == 0) g_off[nNodes] = s_carry;
}

__global__ void scatter_kernel(const int* __restrict__ dst, int nE)
{
    int e = blockIdx.x * blockDim.x + threadIdx.x;
    if (e < nE) {
        int p = atomicAdd(&g_cur[dst[e]], 1);
        g_csr[p] = e;
    }
}

// ------------------------- per-node gather-max (fp16 g_B rows, edge loop unrolled 2x) -------------------------
__global__ __launch_bounds__(256) void agg_kernel(
    const int* __restrict__ src, const float* __restrict__ ew,
    const float* __restrict__ Wm, const float* __restrict__ bm,
    int nNodes)
{
    const int warpId = (blockIdx.x * blockDim.x + threadIdx.x) >> 5;
    const int lane = threadIdx.x & 31;
    if (warpId >= nNodes) return;
    const int n = warpId;
    const float4 ww4 = *(const float4*)(Wm + 256 * HID + lane * 4);
    const int s0 = g_off[n], s1 = g_off[n + 1];
    float4 m = make_float4(-FLT_MAX, -FLT_MAX, -FLT_MAX, -FLT_MAX);
    for (int base = s0; base < s1; base += 32) {
        const int idx = base + lane;
        int sv = 0; float wv = 0.f;
        if (idx < s1) {
            const int e = g_csr[idx];
            sv = src[e];
            wv = ew[e];
        }
        const int cnt = min(32, s1 - base);
        int j = 0;
        for (; j + 1 < cnt; j += 2) {
            const int   sj0 = __shfl_sync(0xffffffffu, sv, j);
            const float wj0 = __shfl_sync(0xffffffffu, wv, j);
            const int   sj1 = __shfl_sync(0xffffffffu, sv, j + 1);
            const float wj1 = __shfl_sync(0xffffffffu, wv, j + 1);
            const uint2 h0 = *(const uint2*)(g_Bh + (size_t)sj0 * (HID/2) + lane * 2);
            const uint2 h1 = *(const uint2*)(g_Bh + (size_t)sj1 * (HID/2) + lane * 2);
            const float2 b0a = __half22float2(*(const __half2*)&h0.x);
            const float2 b0b = __half22float2(*(const __half2*)&h0.y);
            const float2 b1a = __half22float2(*(const __half2*)&h1.x);
            const float2 b1b = __half22float2(*(const __half2*)&h1.y);
            m.x = fmaxf(m.x, fmaf(wj0, ww4.x, b0a.x));
            m.y = fmaxf(m.y, fmaf(wj0, ww4.y, b0a.y));
            m.z = fmaxf(m.z, fmaf(wj0, ww4.z, b0b.x));
            m.w = fmaxf(m.w, fmaf(wj0, ww4.w, b0b.y));
            m.x = fmaxf(m.x, fmaf(wj1, ww4.x, b1a.x));
            m.y = fmaxf(m.y, fmaf(wj1, ww4.y, b1a.y));
            m.z = fmaxf(m.z, fmaf(wj1, ww4.z, b1b.x));
            m.w = fmaxf(m.w, fmaf(wj1, ww4.w, b1b.y));
        }
        if (j < cnt) {
            const int   sj = __shfl_sync(0xffffffffu, sv, j);
            const float wj = __shfl_sync(0xffffffffu, wv, j);
            const uint2 h0 = *(const uint2*)(g_Bh + (size_t)sj * (HID/2) + lane * 2);
            const float2 b0a = __half22float2(*(const __half2*)&h0.x);
            const float2 b0b = __half22float2(*(const __half2*)&h0.y);
            m.x = fmaxf(m.x, fmaf(wj, ww4.x, b0a.x));
            m.y = fmaxf(m.y, fmaf(wj, ww4.y, b0a.y));
            m.z = fmaxf(m.z, fmaf(wj, ww4.z, b0b.x));
            m.w = fmaxf(m.w, fmaf(wj, ww4.w, b0b.y));
        }
    }
    uint2 o;
    if (s1 > s0) {
        const float4 a4 = *(const float4*)(g_A + (size_t)n * HID + lane * 4);
        const float4 bm4 = *(const float4*)(bm + lane * 4);
        const __half2 o01 = __floats2half2_rn(a4.x + bm4.x + m.x, a4.y + bm4.y + m.y);
        const __half2 o23 = __floats2half2_rn(a4.z + bm4.z + m.z, a4.w + bm4.w + m.w);
        o.x = *(const uint32_t*)&o01;
        o.y = *(const uint32_t*)&o23;
    } else {
        o.x = 0u; o.y = 0u;
    }
    *(uint2*)(g_aggh + (size_t)n * (HID/2) + lane * 2) = o;
}

// ------------------------- launch -------------------------
extern "C" void kernel_launch(void* const* d_in, const int* in_sizes, int n_in,
                              void* d_out, int out_size)
{
    const float* z   = (const float*)d_in[0];
    const float* ew  = (const float*)d_in[1];
    const int*   esrc= (const int*)d_in[2];
    const int*   edst= (const int*)d_in[3];
    const float* Wm  = (const float*)d_in[4];
    const float* bm  = (const float*)d_in[5];
    const float* W1  = (const float*)d_in[6];
    const float* b1  = (const float*)d_in[7];
    const float* W2  = (const float*)d_in[8];
    const float* b2  = (const float*)d_in[9];
    float* out = (float*)d_out;

    const int nNodes = in_sizes[0] / HID;
    const int nEdges = in_sizes[1];

    cudaFuncSetAttribute(gemm2_kernel, cudaFuncAttributeMaxDynamicSharedMemorySize, GEMM2_SMEM);
    cudaFuncSetAttribute(fused_mlp_kernel, cudaFuncAttributeMaxDynamicSharedMemorySize, FUSED_SMEM);

    // lazily-created side stream + fork/join events (host-side objects, no device mem)
    static cudaStream_t s_side = nullptr;
    static cudaEvent_t  s_evFork = nullptr, s_evCsr = nullptr;
    if (!s_side) {
        cudaStreamCreateWithFlags(&s_side, cudaStreamNonBlocking);
        cudaEventCreateWithFlags(&s_evFork, cudaEventDisableTiming);
        cudaEventCreateWithFlags(&s_evCsr, cudaEventDisableTiming);
    }

    const int gemmGrid = (nNodes + 127) / 128;
    const int edgeGrid = (nEdges + 255) / 256;
    const int nodeGrid = (nNodes + 255) / 256;
    const int aggGrid  = (nNodes + 7) / 8;

    // fork: CSR build (edge-only inputs) runs concurrently with weight prep + gemm2
    cudaEventRecord(s_evFork, 0);
    cudaStreamWaitEvent(s_side, s_evFork, 0);

    // side stream: CSR build
    zero_deg_kernel<<<nodeGrid, 256, 0, s_side>>>(nNodes);
    deg_kernel<<<edgeGrid, 256, 0, s_side>>>(edst, nEdges);
    scan_kernel<<<1, 1024, 0, s_side>>>(nNodes);
    scatter_kernel<<<edgeGrid, 256, 0, s_side>>>(edst, nEdges);
    cudaEventRecord(s_evCsr, s_side);

    // main stream: prep weights (fp16 transpose), then dual projection
    prep_weights<<<128, 256>>>(Wm, W1, W2);
    gemm2_kernel<<<gemmGrid, 256, GEMM2_SMEM>>>(z, nNodes);

    // join: agg needs both CSR and g_A/g_Bh
    cudaStreamWaitEvent(0, s_evCsr, 0);

    // segment max (gather form, fp16 rows)
    agg_kernel<<<aggGrid, 256>>>(esrc, ew, Wm, bm, nNodes);

    // fused: hidden = relu([z|agg]@W1 + b1); out = hidden@W2 + b2
    fused_mlp_kernel<<<gemmGrid, 256, FUSED_SMEM>>>(z, b1, b2, out, nNodes);
}